// round 13
// baseline (speedup 1.0000x reference)
#include <cuda_runtime.h>
#include <math.h>

#define BB 64
#define SS 512
#define DD 1024
#define HH 1024
#define HH2 512
#define G3 1536
#define GINK 2080
#define SPKD 16
#define NBLK 148
#define NTHR 256

// tile decompositions (work-stealing)
#define KSG 23
#define NT_GATE (32 * KSG)   // 32 N-tiles(128) x 23 K-chunks(96), K padded 2208
#define KSE 32
#define NT_EMO (8 * KSE)     // 8 N-tiles(128) x 32 K-chunks(32)
#define KSR 16
#define NT_GRU (2 * 12 * KSR) // dir x 12 N-tiles(128) x 16 K-chunks(32)

typedef unsigned long long ull;
union F2U { ull u; float2 f; };

#define FMA2(d, a, b) \
    asm("fma.rn.f32x2 %0, %1, %2, %0;" : "+l"(d) : "l"(a), "l"(b))

__device__ __forceinline__ ull dup2(float a) {
    ull d;
    asm("mov.b64 %0, {%1, %1};" : "=l"(d) : "f"(a));
    return d;
}

// ---------------- scratch (device globals; no allocation allowed) ----------------
static __device__ float g_xproj[(size_t)2 * SS * BB * G3];   // [dir][t][b][1536]
static __device__ float g_mem[(size_t)SS * BB * HH];          // [t][b][1024]
static __device__ float g_ghp[(size_t)KSR * 2 * BB * G3];     // GRU gemm partials
static __device__ float g_gpre[(size_t)KSG * BB * 4096];      // gate gemm partials
static __device__ float g_gated[(size_t)BB * HH];
static __device__ float g_h1p[(size_t)KSE * BB * HH];         // emo gemm1 partials
static __device__ float g_hln[(size_t)BB * HH];
static __device__ float g_o2p[(size_t)KSE * BB * HH];         // emo gemm2 partials
static __device__ unsigned int g_bar;
static __device__ unsigned int g_tk[16];                      // ticket slots

__global__ void reset_bar_k() {
    g_bar = 0u;
    for (int i = 0; i < 16; i++) g_tk[i] = 0u;
}

// monotonic atomic grid barrier: all NBLK blocks co-resident
__device__ __forceinline__ void gsync(unsigned int& bar_id) {
    __syncthreads();
    if (threadIdx.x == 0) {
        __threadfence();
        atomicAdd(&g_bar, 1u);
        bar_id++;
        const unsigned int target = bar_id * NBLK;
        while (*((volatile unsigned int*)&g_bar) < target) {
            __nanosleep(20);
        }
        __threadfence();
    }
    __syncthreads();
}

__device__ __forceinline__ float sigm(float x) { return 1.f / (1.f + expf(-x)); }

// ---- M=64 x N=128 microkernel: 4m x 4 n-pairs per thread, broadcast-A ----
// tx = tid&15, ty = tid>>4; m = ty*4+i; col = 2*tx + 32*jp.
__device__ __forceinline__ void mk128(ull (&acc)[4][4],
                                      const float (*As)[68],
                                      const float (*Ws)[132],
                                      int tx, int ty) {
#pragma unroll
    for (int kk = 0; kk < 16; kk++) {
        float4 av = *(const float4*)&As[kk][ty * 4];
        ull a2[4];
        a2[0] = dup2(av.x); a2[1] = dup2(av.y);
        a2[2] = dup2(av.z); a2[3] = dup2(av.w);
        ull b2[4];
#pragma unroll
        for (int jp = 0; jp < 4; jp++)
            b2[jp] = *(const ull*)&Ws[kk][2 * tx + 32 * jp];
#pragma unroll
        for (int i = 0; i < 4; i++)
#pragma unroll
            for (int jp = 0; jp < 4; jp++)
                FMA2(acc[i][jp], a2[i], b2[jp]);
    }
}

// ---------------- big GEMM: x_proj = x @ Wih.T + bih (both dirs; unchanged R7) ----------------
__global__ __launch_bounds__(256) void xproj_kernel(
    const float* __restrict__ uf,
    const float* __restrict__ Wf_, const float* __restrict__ bf_,
    const float* __restrict__ Wb_, const float* __restrict__ bb_)
{
    __shared__ __align__(16) float As[16][132];
    __shared__ __align__(16) float Ws[16][132];
    const int tid = threadIdx.x;
    const int tx = tid & 15, ty = tid >> 4;
    const int Mbase = blockIdx.x * 128;
    const int Nbase = blockIdx.y * 128;
    const int dir = blockIdx.z;
    const float* W = dir ? Wb_ : Wf_;
    const float* bias = dir ? bb_ : bf_;

    const float* ap[8];
    const float* wp[8];
#pragma unroll
    for (int p = 0; p < 8; p++) {
        int i = tid + p * 256;
        int m = i >> 4, k = i & 15;
        int mg = Mbase + m;
        int tt = mg >> 6, b = mg & 63;
        int srow = dir ? (SS - 1 - tt) : tt;
        ap[p] = uf + ((size_t)b * SS + srow) * DD + k;
        wp[p] = W + (size_t)(Nbase + m) * DD + k;
    }

    ull acc[8][4];
#pragma unroll
    for (int i = 0; i < 8; i++)
#pragma unroll
        for (int j = 0; j < 4; j++) acc[i][j] = 0ull;

    float va[8], vw[8];
#pragma unroll
    for (int p = 0; p < 8; p++) { va[p] = ap[p][0]; vw[p] = wp[p][0]; }

    for (int kt = 0; kt < DD; kt += 16) {
        __syncthreads();
#pragma unroll
        for (int p = 0; p < 8; p++) {
            int i = tid + p * 256;
            As[i & 15][i >> 4] = va[p];
            Ws[i & 15][i >> 4] = vw[p];
        }
        __syncthreads();
        if (kt + 16 < DD) {
#pragma unroll
            for (int p = 0; p < 8; p++) {
                va[p] = ap[p][kt + 16];
                vw[p] = wp[p][kt + 16];
            }
        }
#pragma unroll
        for (int kk = 0; kk < 16; kk++) {
            float4 alo = *(const float4*)&As[kk][ty * 8];
            float4 ahi = *(const float4*)&As[kk][ty * 8 + 4];
            ull a2[8];
            a2[0] = dup2(alo.x); a2[1] = dup2(alo.y);
            a2[2] = dup2(alo.z); a2[3] = dup2(alo.w);
            a2[4] = dup2(ahi.x); a2[5] = dup2(ahi.y);
            a2[6] = dup2(ahi.z); a2[7] = dup2(ahi.w);
            ull b2[4];
#pragma unroll
            for (int jp = 0; jp < 4; jp++)
                b2[jp] = *(const ull*)&Ws[kk][2 * tx + 32 * jp];
#pragma unroll
            for (int i = 0; i < 8; i++)
#pragma unroll
                for (int jp = 0; jp < 4; jp++)
                    FMA2(acc[i][jp], a2[i], b2[jp]);
        }
    }

#pragma unroll
    for (int i = 0; i < 8; i++) {
        int mg = Mbase + ty * 8 + i;
        size_t rowb = ((size_t)dir * SS * BB + mg) * G3;
#pragma unroll
        for (int jp = 0; jp < 4; jp++) {
            int col = Nbase + 2 * tx + 32 * jp;
            F2U u; u.u = acc[i][jp];
            u.f.x += bias[col];
            u.f.y += bias[col + 1];
            *(float2*)&g_xproj[rowb + col] = u.f;
        }
    }
}

// ---------------- GRU tile body: (dir, nt[128], ks[32]) ----------------
__device__ __forceinline__ void gru_tile(unsigned tk, int t,
    const float* __restrict__ Whh_f, const float* __restrict__ Whh_b,
    float (*As)[68], float (*Ws)[132], int tx, int ty)
{
    const int tid = threadIdx.x;
    const int dir = tk / (12 * KSR);
    const int rem = tk % (12 * KSR);
    const int nt = rem / KSR;
    const int ks = rem % KSR;
    const float* W = dir ? Whh_b : Whh_f;
    const int Nbase = nt * 128;
    const int k0 = ks * 32;

    ull acc[4][4];
#pragma unroll
    for (int i = 0; i < 4; i++)
#pragma unroll
        for (int j = 0; j < 4; j++) acc[i][j] = 0ull;

    float va[4], vw[8];
#pragma unroll
    for (int p = 0; p < 4; p++) {
        int i = tid + p * 256;
        int m = i >> 4, kg = k0 + (i & 15);
        float v = 0.f;
        if (t > 0)
            v = dir ? g_mem[((size_t)(SS - t) * BB + m) * HH + HH2 + kg]
                    : g_mem[((size_t)(t - 1) * BB + m) * HH + kg];
        va[p] = v;
    }
#pragma unroll
    for (int p = 0; p < 8; p++) {
        int i = tid + p * 256;
        int n = i >> 4, kg = k0 + (i & 15);
        vw[p] = W[(size_t)(Nbase + n) * HH2 + kg];
    }

#pragma unroll
    for (int kt2 = 0; kt2 < 2; kt2++) {
        __syncthreads();
#pragma unroll
        for (int p = 0; p < 4; p++) {
            int i = tid + p * 256;
            As[i & 15][i >> 4] = va[p];
        }
#pragma unroll
        for (int p = 0; p < 8; p++) {
            int i = tid + p * 256;
            Ws[i & 15][i >> 4] = vw[p];
        }
        __syncthreads();
        if (kt2 == 0) {
#pragma unroll
            for (int p = 0; p < 4; p++) {
                int i = tid + p * 256;
                int m = i >> 4, kg = k0 + 16 + (i & 15);
                float v = 0.f;
                if (t > 0)
                    v = dir ? g_mem[((size_t)(SS - t) * BB + m) * HH + HH2 + kg]
                            : g_mem[((size_t)(t - 1) * BB + m) * HH + kg];
                va[p] = v;
            }
#pragma unroll
            for (int p = 0; p < 8; p++) {
                int i = tid + p * 256;
                int n = i >> 4, kg = k0 + 16 + (i & 15);
                vw[p] = W[(size_t)(Nbase + n) * HH2 + kg];
            }
        }
        mk128(acc, (const float (*)[68])As, (const float (*)[132])Ws, tx, ty);
    }
#pragma unroll
    for (int i2 = 0; i2 < 4; i2++) {
        int m = ty * 4 + i2;
        size_t rowb = (((size_t)ks * 2 + dir) * BB + m) * G3;
#pragma unroll
        for (int jp = 0; jp < 4; jp++) {
            int col = Nbase + 2 * tx + 32 * jp;
            F2U u; u.u = acc[i2][jp];
            *(float2*)&g_ghp[rowb + col] = u.f;
        }
    }
}

// ---------------- gate tile body: (nt[128] of 4096, ks[96] of 2208 pad) ----------------
__device__ __forceinline__ void gate_tile(unsigned tk, int t,
    const float* __restrict__ Wf, const float* __restrict__ Wi,
    const float* __restrict__ Wo, const float* __restrict__ Wc,
    const float* __restrict__ outp, const float* __restrict__ spk,
    const float* __restrict__ pos,
    float (*As)[68], float (*Ws)[132], int tx, int ty)
{
    const int tid = threadIdx.x;
    const int nt = tk / KSG;
    const int ks = tk % KSG;
    const int Nbase = nt * 128;
    const int gate = Nbase >> 10;
    const float* W = (gate == 0) ? Wf : (gate == 1) ? Wi : (gate == 2) ? Wo : Wc;
    const int wrow = Nbase & 1023;
    const int k0 = ks * 96;

    ull acc[4][4];
#pragma unroll
    for (int i = 0; i < 4; i++)
#pragma unroll
        for (int j = 0; j < 4; j++) acc[i][j] = 0ull;

    float va[4], vw[8];
#pragma unroll
    for (int p = 0; p < 4; p++) {
        int i = tid + p * 256;
        int m = i >> 4, kg = k0 + (i & 15);
        float v = 0.f;
        if (kg < 1024)      v = g_mem[((size_t)t * BB + m) * HH + kg];
        else if (kg < 2048) v = outp[((size_t)m * SS + (t - 1)) * HH + (kg - 1024)];
        else if (kg < 2064) v = spk[((size_t)m * SS + t) * SPKD + (kg - 2048)];
        else if (kg < 2080) v = pos[((size_t)m * SS + t) * SPKD + (kg - 2064)];
        va[p] = v;
    }
#pragma unroll
    for (int p = 0; p < 8; p++) {
        int i = tid + p * 256;
        int n = i >> 4, kg = k0 + (i & 15);
        vw[p] = (kg < GINK) ? W[(size_t)(wrow + n) * GINK + kg] : 0.f;
    }

    for (int kt = k0; kt < k0 + 96; kt += 16) {
        __syncthreads();
#pragma unroll
        for (int p = 0; p < 4; p++) {
            int i = tid + p * 256;
            As[i & 15][i >> 4] = va[p];
        }
#pragma unroll
        for (int p = 0; p < 8; p++) {
            int i = tid + p * 256;
            Ws[i & 15][i >> 4] = vw[p];
        }
        __syncthreads();
        if (kt + 16 < k0 + 96) {
#pragma unroll
            for (int p = 0; p < 4; p++) {
                int i = tid + p * 256;
                int m = i >> 4, kg = kt + 16 + (i & 15);
                float v = 0.f;
                if (kg < 1024)      v = g_mem[((size_t)t * BB + m) * HH + kg];
                else if (kg < 2048) v = outp[((size_t)m * SS + (t - 1)) * HH + (kg - 1024)];
                else if (kg < 2064) v = spk[((size_t)m * SS + t) * SPKD + (kg - 2048)];
                else if (kg < 2080) v = pos[((size_t)m * SS + t) * SPKD + (kg - 2064)];
                va[p] = v;
            }
#pragma unroll
            for (int p = 0; p < 8; p++) {
                int i = tid + p * 256;
                int n = i >> 4, kg = kt + 16 + (i & 15);
                vw[p] = (kg < GINK) ? W[(size_t)(wrow + n) * GINK + kg] : 0.f;
            }
        }
        mk128(acc, (const float (*)[68])As, (const float (*)[132])Ws, tx, ty);
    }
#pragma unroll
    for (int i2 = 0; i2 < 4; i2++) {
        int m = ty * 4 + i2;
        size_t rowb = ((size_t)ks * BB + m) * 4096;
#pragma unroll
        for (int jp = 0; jp < 4; jp++) {
            int col = Nbase + 2 * tx + 32 * jp;
            F2U u; u.u = acc[i2][jp];
            *(float2*)&g_gpre[rowb + col] = u.f;
        }
    }
}

// ---------------- emo tile body: (nt[128] of 1024, ks[32] of 1024) ----------------
template <int AMODE>
__device__ __forceinline__ void emo_tile(unsigned tk, int t,
    const float* __restrict__ W, float* __restrict__ dst,
    float (*As)[68], float (*Ws)[132], int tx, int ty)
{
    const int tid = threadIdx.x;
    const int nt = tk >> 5;
    const int ks = tk & 31;
    const int Nbase = nt * 128;
    const int k0 = ks * 32;

    ull acc[4][4];
#pragma unroll
    for (int i = 0; i < 4; i++)
#pragma unroll
        for (int j = 0; j < 4; j++) acc[i][j] = 0ull;

    float va[4], vw[8];
#pragma unroll
    for (int p = 0; p < 4; p++) {
        int i = tid + p * 256;
        int m = i >> 4, kg = k0 + (i & 15);
        float v;
        if (AMODE == 0)
            v = (t == 0) ? g_mem[(size_t)m * HH + kg] : g_gated[(size_t)m * HH + kg];
        else
            v = g_hln[(size_t)m * HH + kg];
        va[p] = v;
    }
#pragma unroll
    for (int p = 0; p < 8; p++) {
        int i = tid + p * 256;
        int n = i >> 4, kg = k0 + (i & 15);
        vw[p] = W[(size_t)(Nbase + n) * HH + kg];
    }

#pragma unroll
    for (int kt2 = 0; kt2 < 2; kt2++) {
        __syncthreads();
#pragma unroll
        for (int p = 0; p < 4; p++) {
            int i = tid + p * 256;
            As[i & 15][i >> 4] = va[p];
        }
#pragma unroll
        for (int p = 0; p < 8; p++) {
            int i = tid + p * 256;
            Ws[i & 15][i >> 4] = vw[p];
        }
        __syncthreads();
        if (kt2 == 0) {
#pragma unroll
            for (int p = 0; p < 4; p++) {
                int i = tid + p * 256;
                int m = i >> 4, kg = k0 + 16 + (i & 15);
                float v;
                if (AMODE == 0)
                    v = (t == 0) ? g_mem[(size_t)m * HH + kg] : g_gated[(size_t)m * HH + kg];
                else
                    v = g_hln[(size_t)m * HH + kg];
                va[p] = v;
            }
#pragma unroll
            for (int p = 0; p < 8; p++) {
                int i = tid + p * 256;
                int n = i >> 4, kg = k0 + 16 + (i & 15);
                vw[p] = W[(size_t)(Nbase + n) * HH + kg];
            }
        }
        mk128(acc, (const float (*)[68])As, (const float (*)[132])Ws, tx, ty);
    }
#pragma unroll
    for (int i2 = 0; i2 < 4; i2++) {
        int m = ty * 4 + i2;
        size_t rowb = ((size_t)ks * BB + m) * HH;
#pragma unroll
        for (int jp = 0; jp < 4; jp++) {
            int col = Nbase + 2 * tx + 32 * jp;
            F2U u; u.u = acc[i2][jp];
            *(float2*)&dst[rowb + col] = u.f;
        }
    }
}

// stealing loop macro: draws tickets from slot, runs BODY(tk)
#define STEAL_LOOP(slot, NT, BODY)                                   \
    for (;;) {                                                       \
        __syncthreads();                                             \
        if (tid == 0) s_tile = atomicAdd(&g_tk[slot], 1u);           \
        __syncthreads();                                             \
        unsigned _tk = s_tile;                                       \
        if (_tk >= (NT)) break;                                      \
        BODY(_tk);                                                   \
    }

// slot bookkeeping after the phase's gsync
#define SLOT_NEXT()                                                  \
    do {                                                             \
        if (bx == 0 && tid == 0) g_tk[(ts + 8) & 15] = 0u;           \
        ts++;                                                        \
    } while (0)

// ---------------- persistent GRU: 512 steps ----------------
__global__ __launch_bounds__(NTHR, 1) void gru_persistent(
    const float* __restrict__ Whh_f, const float* __restrict__ Whh_b,
    const float* __restrict__ bhh_f, const float* __restrict__ bhh_b)
{
    __shared__ __align__(16) float As[16][68];
    __shared__ __align__(16) float Ws[16][132];
    __shared__ unsigned s_tile;
    const int tid = threadIdx.x;
    const int tx = tid & 15, ty = tid >> 4;
    const int bx = blockIdx.x;
    unsigned int bar_id = 0;
    unsigned int ts = 0;

    for (int t = 0; t < SS; t++) {
#define GRU_BODY(tk) gru_tile(tk, t, Whh_f, Whh_b, As, Ws, tx, ty)
        STEAL_LOOP((ts & 15), NT_GRU, GRU_BODY)
#undef GRU_BODY
        gsync(bar_id);
        SLOT_NEXT();

        // combine: 2*64*512 = 65536 elems
        for (int e = bx * NTHR + tid; e < 2 * BB * HH2; e += NBLK * NTHR) {
            int d2 = e >> 15;
            int b = (e >> 9) & 63;
            int i = e & 511;
            const float* bhh = d2 ? bhh_b : bhh_f;
            float hr = bhh[i], hz = bhh[HH2 + i], hn = bhh[2 * HH2 + i];
#pragma unroll
            for (int q = 0; q < KSR; q++) {
                size_t base = (((size_t)q * 2 + d2) * BB + b) * G3;
                hr += g_ghp[base + i];
                hz += g_ghp[base + HH2 + i];
                hn += g_ghp[base + 2 * HH2 + i];
            }
            size_t xb = (((size_t)d2 * SS + t) * BB + b) * G3;
            float xr = g_xproj[xb + i], xz = g_xproj[xb + HH2 + i], xn = g_xproj[xb + 2 * HH2 + i];
            float hp = 0.f;
            if (t > 0)
                hp = d2 ? g_mem[((size_t)(SS - t) * BB + b) * HH + HH2 + i]
                        : g_mem[((size_t)(t - 1) * BB + b) * HH + i];
            float r = sigm(xr + hr);
            float z = sigm(xz + hz);
            float n2 = tanhf(xn + r * hn);
            float h = (1.f - z) * n2 + z * hp;
            if (d2 == 0) g_mem[((size_t)t * BB + b) * HH + i] = h;
            else         g_mem[((size_t)(SS - 1 - t) * BB + b) * HH + HH2 + i] = h;
        }
        gsync(bar_id);
    }
}

// ---------------- persistent gating kernel: 512 steps ----------------
__global__ __launch_bounds__(NTHR, 1) void gating_persistent(
    const float* __restrict__ spk, const float* __restrict__ pos,
    const float* __restrict__ Wfw, const float* __restrict__ bfb,
    const float* __restrict__ Wiw, const float* __restrict__ bib,
    const float* __restrict__ Wow, const float* __restrict__ bob,
    const float* __restrict__ Wcw, const float* __restrict__ bcb,
    const float* __restrict__ W1e, const float* __restrict__ b1e,
    const float* __restrict__ gln, const float* __restrict__ beta,
    const float* __restrict__ W2e, const float* __restrict__ b2e,
    float* __restrict__ out)
{
    __shared__ __align__(16) float As[16][68];
    __shared__ __align__(16) float Ws[16][132];
    __shared__ float sred[NTHR];
    __shared__ float stats[2];
    __shared__ unsigned s_tile;
    const int tid = threadIdx.x;
    const int tx = tid & 15, ty = tid >> 4;
    const int bx = blockIdx.x;
    unsigned int bar_id = 0;
    unsigned int ts = 0;

    for (int t = 0; t < SS; t++) {
        if (t > 0) {
#define GATE_BODY(tk) gate_tile(tk, t, Wfw, Wiw, Wow, Wcw, out, spk, pos, As, Ws, tx, ty)
            STEAL_LOOP((ts & 15), NT_GATE, GATE_BODY)
#undef GATE_BODY
            gsync(bar_id);
            SLOT_NEXT();

            // gate combine -> g_gated
            for (int e = bx * NTHR + tid; e < BB * HH; e += NBLK * NTHR) {
                int b = e >> 10, i = e & 1023;
                float f = bfb[i], ig = bib[i], o = bob[i], c = bcb[i];
#pragma unroll
                for (int q = 0; q < KSG; q++) {
                    size_t base = ((size_t)q * BB + b) * 4096;
                    f  += g_gpre[base + i];
                    ig += g_gpre[base + 1024 + i];
                    o  += g_gpre[base + 2048 + i];
                    c  += g_gpre[base + 3072 + i];
                }
                float prev = out[((size_t)b * SS + (t - 1)) * HH + i];
                f = sigm(f); ig = sigm(ig); o = sigm(o); c = tanhf(c);
                g_gated[e] = o * tanhf(f * prev + ig * c);
            }
            gsync(bar_id);
        }

        // emo GEMM1 (stolen tiles)
#define EMO1_BODY(tk) emo_tile<0>(tk, t, W1e, g_h1p, As, Ws, tx, ty)
        STEAL_LOOP((ts & 15), NT_EMO, EMO1_BODY)
#undef EMO1_BODY
        gsync(bar_id);
        SLOT_NEXT();

        // LayerNorm + ReLU (blocks 0..63)
        if (bx < BB) {
            const int b = bx;
            float v[4];
            float lsum = 0.f, lsq = 0.f;
#pragma unroll
            for (int j = 0; j < 4; j++) {
                int i = tid + j * NTHR;
                float x = b1e[i];
#pragma unroll
                for (int q = 0; q < KSE; q++) x += g_h1p[((size_t)q * BB + b) * HH + i];
                v[j] = x; lsum += x; lsq += x * x;
            }
            sred[tid] = lsum; __syncthreads();
            for (int s2 = NTHR / 2; s2 > 0; s2 >>= 1) {
                if (tid < s2) sred[tid] += sred[tid + s2];
                __syncthreads();
            }
            if (tid == 0) stats[0] = sred[0] * (1.f / 1024.f);
            __syncthreads();
            sred[tid] = lsq; __syncthreads();
            for (int s2 = NTHR / 2; s2 > 0; s2 >>= 1) {
                if (tid < s2) sred[tid] += sred[tid + s2];
                __syncthreads();
            }
            if (tid == 0) stats[1] = sred[0] * (1.f / 1024.f);
            __syncthreads();
            float mu = stats[0];
            float var = stats[1] - mu * mu;
            float rs = rsqrtf(var + 1e-5f);
#pragma unroll
            for (int j = 0; j < 4; j++) {
                int i = tid + j * NTHR;
                float y = (v[j] - mu) * rs * gln[i] + beta[i];
                g_hln[(size_t)b * HH + i] = y > 0.f ? y : 0.f;
            }
        }
        gsync(bar_id);

        // emo GEMM2 (stolen tiles)
#define EMO2_BODY(tk) emo_tile<1>(tk, t, W2e, g_o2p, As, Ws, tx, ty)
        STEAL_LOOP((ts & 15), NT_EMO, EMO2_BODY)
#undef EMO2_BODY
        gsync(bar_id);
        SLOT_NEXT();

        // finalize out[t]
        for (int e = bx * NTHR + tid; e < BB * HH; e += NBLK * NTHR) {
            int b = e >> 10, i = e & 1023;
            float x = b2e[i];
#pragma unroll
            for (int q = 0; q < KSE; q++) x += g_o2p[((size_t)q * BB + b) * HH + i];
            float res = (t == 0) ? g_mem[(size_t)b * HH + i] : g_gated[e];
            out[((size_t)b * SS + t) * HH + i] = x + res;
        }
        gsync(bar_id);
    }
}

// ---------------- host launcher: 5 graph nodes total ----------------
extern "C" void kernel_launch(void* const* d_in, const int* in_sizes, int n_in,
                              void* d_out, int out_size)
{
    (void)in_sizes; (void)n_in; (void)out_size;
    const float* uf    = (const float*)d_in[0];
    const float* spk   = (const float*)d_in[1];
    const float* pos   = (const float*)d_in[2];
    const float* Wih_f = (const float*)d_in[3];
    const float* Whh_f = (const float*)d_in[4];
    const float* bih_f = (const float*)d_in[5];
    const float* bhh_f = (const float*)d_in[6];
    const float* Wih_b = (const float*)d_in[7];
    const float* Whh_b = (const float*)d_in[8];
    const float* bih_b = (const float*)d_in[9];
    const float* bhh_b = (const float*)d_in[10];
    const float* Wfw   = (const float*)d_in[11];
    const float* bfb   = (const float*)d_in[12];
    const float* Wiw   = (const float*)d_in[13];
    const float* bib   = (const float*)d_in[14];
    const float* Wow   = (const float*)d_in[15];
    const float* bob   = (const float*)d_in[16];
    const float* Wcw   = (const float*)d_in[17];
    const float* bcb   = (const float*)d_in[18];
    const float* W1e   = (const float*)d_in[19];
    const float* b1e   = (const float*)d_in[20];
    const float* g_ln  = (const float*)d_in[21];
    const float* beta  = (const float*)d_in[22];
    const float* W2e   = (const float*)d_in[23];
    const float* b2e   = (const float*)d_in[24];
    float* out = (float*)d_out;

    // 1) x projections for both GRU directions (parallel, big grid)
    xproj_kernel<<<dim3(256, 12, 2), 256>>>(uf, Wih_f, bih_f, Wih_b, bih_b);

    // 2) persistent bidirectional GRU recurrence (work-stealing tiles)
    reset_bar_k<<<1, 1>>>();
    gru_persistent<<<NBLK, NTHR>>>(Whh_f, Whh_b, bhh_f, bhh_b);

    // 3) persistent dialogue gating loop (work-stealing tiles)
    reset_bar_k<<<1, 1>>>();
    gating_persistent<<<NBLK, NTHR>>>(spk, pos, Wfw, bfb, Wiw, bib, Wow, bob,
                                      Wcw, bcb, W1e, b1e, g_ln, beta, W2e, b2e, out);
}

// round 14
// speedup vs baseline: 1.1781x; 1.1781x over previous
#include <cuda_runtime.h>
#include <math.h>

#define BB 64
#define SS 512
#define DD 1024
#define HH 1024
#define HH2 512
#define G3 1536
#define GINK 2080
#define SPKD 16
#define NBLK 148
#define NTHR 256

typedef unsigned long long ull;
union F2U { ull u; float2 f; };

#define FMA2(d, a, b) \
    asm("fma.rn.f32x2 %0, %1, %2, %0;" : "+l"(d) : "l"(a), "l"(b))

__device__ __forceinline__ ull dup2(float a) {
    ull d;
    asm("mov.b64 %0, {%1, %1};" : "=l"(d) : "f"(a));
    return d;
}

// K-split counts (identical to the 37.0ms R7 kernel)
#define KS_GATE 9     // chunk 240 (15 tiles), K padded 2160
#define KS_GRU  11    // chunk 48 (3 tiles), last chunk 32
#define KS_EMO  32    // chunk 32 (2 tiles)

// ---------------- scratch (device globals; no allocation allowed) ----------------
static __device__ float g_xproj[(size_t)2 * SS * BB * G3];   // [dir][t][b][1536]
static __device__ float g_mem[(size_t)SS * BB * HH];          // [t][b][1024]
static __device__ float g_ghp[(size_t)KS_GRU * 2 * BB * G3];  // GRU gemm partials
static __device__ float g_gpre[(size_t)KS_GATE * BB * 4096];  // gate gemm partials
static __device__ float g_gated[(size_t)BB * HH];
static __device__ float g_h1p[(size_t)KS_EMO * BB * HH];      // emo gemm1 partials
static __device__ float g_hln[(size_t)BB * HH];
static __device__ float g_o2p[(size_t)KS_EMO * BB * HH];      // emo gemm2 partials

// two-level barrier state (zero-initialized; monotonic epochs -> replay-safe)
static __device__ unsigned int g_arr[NBLK * 32];   // one flag per block, 128B apart
static __device__ unsigned int g_go;

// Two-level grid barrier:
//  arrive: parallel stores to per-block private lines (no RMW serialization)
//  aggregate: block 0, threads 0..147 poll distinct flags in parallel
//  depart: others poll the single read-only 'go' word (reads don't lock the line)
__device__ __forceinline__ void gsync(unsigned int& ep) {
    __syncthreads();
    ep++;
    if (threadIdx.x == 0) {
        __threadfence();   // release: this block's writes visible at L2
        *((volatile unsigned int*)&g_arr[blockIdx.x * 32]) = ep;
    }
    if (blockIdx.x == 0) {
        if (threadIdx.x < NBLK) {
            while (*((volatile unsigned int*)&g_arr[threadIdx.x * 32]) < ep)
                __nanosleep(32);
        }
        __syncthreads();
        if (threadIdx.x == 0) {
            __threadfence();
            *((volatile unsigned int*)&g_go) = ep;
        }
    } else {
        if (threadIdx.x == 0) {
            while (*((volatile unsigned int*)&g_go) < ep)
                __nanosleep(32);
        }
    }
    __syncthreads();
    if (threadIdx.x == 0) __threadfence();  // acquire: drop stale L1 lines
    __syncthreads();
}

__device__ __forceinline__ float sigm(float x) { return 1.f / (1.f + expf(-x)); }

// ---- M=64 x N=256 microkernel: 8m x 4 n-pairs per thread, broadcast-A ----
__device__ __forceinline__ void mk64(ull (&acc)[8][4],
                                     const float (*As)[68],
                                     const float (*Ws)[260],
                                     int tx, int ty) {
#pragma unroll
    for (int kk = 0; kk < 16; kk++) {
        float4 alo = *(const float4*)&As[kk][ty * 8];
        float4 ahi = *(const float4*)&As[kk][ty * 8 + 4];
        ull a2[8];
        a2[0] = dup2(alo.x); a2[1] = dup2(alo.y);
        a2[2] = dup2(alo.z); a2[3] = dup2(alo.w);
        a2[4] = dup2(ahi.x); a2[5] = dup2(ahi.y);
        a2[6] = dup2(ahi.z); a2[7] = dup2(ahi.w);
        ull b2[4];
#pragma unroll
        for (int jp = 0; jp < 4; jp++)
            b2[jp] = *(const ull*)&Ws[kk][2 * tx + 64 * jp];
#pragma unroll
        for (int i = 0; i < 8; i++)
#pragma unroll
            for (int jp = 0; jp < 4; jp++)
                FMA2(acc[i][jp], a2[i], b2[jp]);
    }
}

// ---------------- big GEMM: x_proj = x @ Wih.T + bih (both dirs) ----------------
__global__ __launch_bounds__(256) void xproj_kernel(
    const float* __restrict__ uf,
    const float* __restrict__ Wf_, const float* __restrict__ bf_,
    const float* __restrict__ Wb_, const float* __restrict__ bb_)
{
    __shared__ __align__(16) float As[16][132];
    __shared__ __align__(16) float Ws[16][132];
    const int tid = threadIdx.x;
    const int tx = tid & 15, ty = tid >> 4;
    const int Mbase = blockIdx.x * 128;
    const int Nbase = blockIdx.y * 128;
    const int dir = blockIdx.z;
    const float* W = dir ? Wb_ : Wf_;
    const float* bias = dir ? bb_ : bf_;

    const float* ap[8];
    const float* wp[8];
#pragma unroll
    for (int p = 0; p < 8; p++) {
        int i = tid + p * 256;
        int m = i >> 4, k = i & 15;
        int mg = Mbase + m;
        int tt = mg >> 6, b = mg & 63;
        int srow = dir ? (SS - 1 - tt) : tt;
        ap[p] = uf + ((size_t)b * SS + srow) * DD + k;
        wp[p] = W + (size_t)(Nbase + m) * DD + k;
    }

    ull acc[8][4];
#pragma unroll
    for (int i = 0; i < 8; i++)
#pragma unroll
        for (int j = 0; j < 4; j++) acc[i][j] = 0ull;

    float va[8], vw[8];
#pragma unroll
    for (int p = 0; p < 8; p++) { va[p] = ap[p][0]; vw[p] = wp[p][0]; }

    for (int kt = 0; kt < DD; kt += 16) {
        __syncthreads();
#pragma unroll
        for (int p = 0; p < 8; p++) {
            int i = tid + p * 256;
            As[i & 15][i >> 4] = va[p];
            Ws[i & 15][i >> 4] = vw[p];
        }
        __syncthreads();
        if (kt + 16 < DD) {
#pragma unroll
            for (int p = 0; p < 8; p++) {
                va[p] = ap[p][kt + 16];
                vw[p] = wp[p][kt + 16];
            }
        }
#pragma unroll
        for (int kk = 0; kk < 16; kk++) {
            float4 alo = *(const float4*)&As[kk][ty * 8];
            float4 ahi = *(const float4*)&As[kk][ty * 8 + 4];
            ull a2[8];
            a2[0] = dup2(alo.x); a2[1] = dup2(alo.y);
            a2[2] = dup2(alo.z); a2[3] = dup2(alo.w);
            a2[4] = dup2(ahi.x); a2[5] = dup2(ahi.y);
            a2[6] = dup2(ahi.z); a2[7] = dup2(ahi.w);
            ull b2[4];
#pragma unroll
            for (int jp = 0; jp < 4; jp++)
                b2[jp] = *(const ull*)&Ws[kk][2 * tx + 32 * jp];
#pragma unroll
            for (int i = 0; i < 8; i++)
#pragma unroll
                for (int jp = 0; jp < 4; jp++)
                    FMA2(acc[i][jp], a2[i], b2[jp]);
        }
    }

#pragma unroll
    for (int i = 0; i < 8; i++) {
        int mg = Mbase + ty * 8 + i;
        size_t rowb = ((size_t)dir * SS * BB + mg) * G3;
#pragma unroll
        for (int jp = 0; jp < 4; jp++) {
            int col = Nbase + 2 * tx + 32 * jp;
            F2U u; u.u = acc[i][jp];
            u.f.x += bias[col];
            u.f.y += bias[col + 1];
            *(float2*)&g_xproj[rowb + col] = u.f;
        }
    }
}

// ---------------- persistent GRU: 512 steps, 2 grid syncs per step ----------------
__global__ __launch_bounds__(NTHR, 1) void gru_persistent(
    const float* __restrict__ Whh_f, const float* __restrict__ Whh_b,
    const float* __restrict__ bhh_f, const float* __restrict__ bhh_b)
{
    __shared__ __align__(16) float As[16][68];
    __shared__ __align__(16) float Ws[16][260];
    const int tid = threadIdx.x;
    const int tx = tid & 31, ty = tid >> 5;
    const int bx = blockIdx.x;
    unsigned int ep = *((volatile unsigned int*)&g_go);

    const int w = bx;
    const bool active = (w < 2 * 6 * KS_GRU);
    const int dir = w / (6 * KS_GRU);
    const int rem = w % (6 * KS_GRU);
    const int nt = rem / KS_GRU;
    const int ks = rem % KS_GRU;
    const float* W = dir ? Whh_b : Whh_f;
    const int Nbase = nt * 256;
    const int k0 = ks * 48;
    const int k1 = (k0 + 48 < HH2) ? (k0 + 48) : HH2;

    for (int t = 0; t < SS; t++) {
        if (active) {
            ull acc[8][4];
#pragma unroll
            for (int i = 0; i < 8; i++)
#pragma unroll
                for (int j = 0; j < 4; j++) acc[i][j] = 0ull;

            float va[4], vw[16];
#pragma unroll
            for (int p = 0; p < 4; p++) {
                int i = tid + p * 256;
                int m = i >> 4, kg = k0 + (i & 15);
                float v = 0.f;
                if (t > 0)
                    v = dir ? g_mem[((size_t)(SS - t) * BB + m) * HH + HH2 + kg]
                            : g_mem[((size_t)(t - 1) * BB + m) * HH + kg];
                va[p] = v;
            }
#pragma unroll
            for (int p = 0; p < 16; p++) {
                int i = tid + p * 256;
                int n = i >> 4, kg = k0 + (i & 15);
                vw[p] = W[(size_t)(Nbase + n) * HH2 + kg];
            }

            for (int kt = k0; kt < k1; kt += 16) {
                __syncthreads();
#pragma unroll
                for (int p = 0; p < 4; p++) {
                    int i = tid + p * 256;
                    As[i & 15][i >> 4] = va[p];
                }
#pragma unroll
                for (int p = 0; p < 16; p++) {
                    int i = tid + p * 256;
                    Ws[i & 15][i >> 4] = vw[p];
                }
                __syncthreads();
                if (kt + 16 < k1) {
#pragma unroll
                    for (int p = 0; p < 4; p++) {
                        int i = tid + p * 256;
                        int m = i >> 4, kg = kt + 16 + (i & 15);
                        float v = 0.f;
                        if (t > 0)
                            v = dir ? g_mem[((size_t)(SS - t) * BB + m) * HH + HH2 + kg]
                                    : g_mem[((size_t)(t - 1) * BB + m) * HH + kg];
                        va[p] = v;
                    }
#pragma unroll
                    for (int p = 0; p < 16; p++) {
                        int i = tid + p * 256;
                        int n = i >> 4, kg = kt + 16 + (i & 15);
                        vw[p] = W[(size_t)(Nbase + n) * HH2 + kg];
                    }
                }
                mk64(acc, As, Ws, tx, ty);
            }
#pragma unroll
            for (int i2 = 0; i2 < 8; i2++) {
                int m = ty * 8 + i2;
                size_t rowb = (((size_t)ks * 2 + dir) * BB + m) * G3;
#pragma unroll
                for (int jp = 0; jp < 4; jp++) {
                    int col = Nbase + 2 * tx + 64 * jp;
                    F2U u; u.u = acc[i2][jp];
                    *(float2*)&g_ghp[rowb + col] = u.f;
                }
            }
        }
        gsync(ep);

        // combine: 2*64*512 = 65536 elems
        for (int e = bx * NTHR + tid; e < 2 * BB * HH2; e += NBLK * NTHR) {
            int d2 = e >> 15;
            int b = (e >> 9) & 63;
            int i = e & 511;
            const float* bhh = d2 ? bhh_b : bhh_f;
            float hr = bhh[i], hz = bhh[HH2 + i], hn = bhh[2 * HH2 + i];
#pragma unroll
            for (int q = 0; q < KS_GRU; q++) {
                size_t base = (((size_t)q * 2 + d2) * BB + b) * G3;
                hr += g_ghp[base + i];
                hz += g_ghp[base + HH2 + i];
                hn += g_ghp[base + 2 * HH2 + i];
            }
            size_t xb = (((size_t)d2 * SS + t) * BB + b) * G3;
            float xr = g_xproj[xb + i], xz = g_xproj[xb + HH2 + i], xn = g_xproj[xb + 2 * HH2 + i];
            float hp = 0.f;
            if (t > 0)
                hp = d2 ? g_mem[((size_t)(SS - t) * BB + b) * HH + HH2 + i]
                        : g_mem[((size_t)(t - 1) * BB + b) * HH + i];
            float r = sigm(xr + hr);
            float z = sigm(xz + hz);
            float n2 = tanhf(xn + r * hn);
            float h = (1.f - z) * n2 + z * hp;
            if (d2 == 0) g_mem[((size_t)t * BB + b) * HH + i] = h;
            else         g_mem[((size_t)(SS - 1 - t) * BB + b) * HH + HH2 + i] = h;
        }
        gsync(ep);
    }
}

// ---------------- emo GEMM phase: N=1024 (4 tiles of 256), K=1024 (32 chunks of 32) ----------------
template <int AMODE>
__device__ __forceinline__ void emo_gemm(int t, const float* __restrict__ W,
                                         float* __restrict__ dst,
                                         float (*As)[68], float (*Ws)[260],
                                         int tx, int ty)
{
    const int tid = threadIdx.x;
    const int w = blockIdx.x;
    if (w >= 4 * KS_EMO) return;
    const int nt = w >> 5;
    const int ks = w & 31;
    const int Nbase = nt * 256;
    const int k0 = ks * 32;

    ull acc[8][4];
#pragma unroll
    for (int i = 0; i < 8; i++)
#pragma unroll
        for (int j = 0; j < 4; j++) acc[i][j] = 0ull;

    float va[4], vw[16];
#pragma unroll
    for (int p = 0; p < 4; p++) {
        int i = tid + p * 256;
        int m = i >> 4, kg = k0 + (i & 15);
        float v;
        if (AMODE == 0)
            v = (t == 0) ? g_mem[(size_t)m * HH + kg] : g_gated[(size_t)m * HH + kg];
        else
            v = g_hln[(size_t)m * HH + kg];
        va[p] = v;
    }
#pragma unroll
    for (int p = 0; p < 16; p++) {
        int i = tid + p * 256;
        int n = i >> 4, kg = k0 + (i & 15);
        vw[p] = W[(size_t)(Nbase + n) * HH + kg];
    }

    for (int kt = k0; kt < k0 + 32; kt += 16) {
        __syncthreads();
#pragma unroll
        for (int p = 0; p < 4; p++) {
            int i = tid + p * 256;
            As[i & 15][i >> 4] = va[p];
        }
#pragma unroll
        for (int p = 0; p < 16; p++) {
            int i = tid + p * 256;
            Ws[i & 15][i >> 4] = vw[p];
        }
        __syncthreads();
        if (kt + 16 < k0 + 32) {
#pragma unroll
            for (int p = 0; p < 4; p++) {
                int i = tid + p * 256;
                int m = i >> 4, kg = kt + 16 + (i & 15);
                float v;
                if (AMODE == 0)
                    v = (t == 0) ? g_mem[(size_t)m * HH + kg] : g_gated[(size_t)m * HH + kg];
                else
                    v = g_hln[(size_t)m * HH + kg];
                va[p] = v;
            }
#pragma unroll
            for (int p = 0; p < 16; p++) {
                int i = tid + p * 256;
                int n = i >> 4, kg = kt + 16 + (i & 15);
                vw[p] = W[(size_t)(Nbase + n) * HH + kg];
            }
        }
        mk64(acc, (const float (*)[68])As, (const float (*)[260])Ws, tx, ty);
    }
#pragma unroll
    for (int i2 = 0; i2 < 8; i2++) {
        int m = ty * 8 + i2;
        size_t rowb = ((size_t)ks * BB + m) * HH;
#pragma unroll
        for (int jp = 0; jp < 4; jp++) {
            int col = Nbase + 2 * tx + 64 * jp;
            F2U u; u.u = acc[i2][jp];
            *(float2*)&dst[rowb + col] = u.f;
        }
    }
}

// ---------------- gate GEMM phase: N=4096 (16 tiles of 256), K=2080 pad 2160 (9 chunks of 240) ----------------
__device__ __forceinline__ void gate_gemm(int t,
    const float* __restrict__ Wf, const float* __restrict__ Wi,
    const float* __restrict__ Wo, const float* __restrict__ Wc,
    const float* __restrict__ outp, const float* __restrict__ spk,
    const float* __restrict__ pos,
    float (*As)[68], float (*Ws)[260], int tx, int ty)
{
    const int tid = threadIdx.x;
    const int w = blockIdx.x;
    if (w >= 16 * KS_GATE) return;
    const int nt = w / KS_GATE;
    const int ks = w % KS_GATE;
    const int Nbase = nt * 256;
    const int gate = Nbase >> 10;
    const float* W = (gate == 0) ? Wf : (gate == 1) ? Wi : (gate == 2) ? Wo : Wc;
    const int wrow = Nbase & 1023;
    const int k0 = ks * 240;

    ull acc[8][4];
#pragma unroll
    for (int i = 0; i < 8; i++)
#pragma unroll
        for (int j = 0; j < 4; j++) acc[i][j] = 0ull;

    float va[4], vw[16];
#pragma unroll
    for (int p = 0; p < 4; p++) {
        int i = tid + p * 256;
        int m = i >> 4, kg = k0 + (i & 15);
        float v = 0.f;
        if (kg < 1024)      v = g_mem[((size_t)t * BB + m) * HH + kg];
        else if (kg < 2048) v = outp[((size_t)m * SS + (t - 1)) * HH + (kg - 1024)];
        else if (kg < 2064) v = spk[((size_t)m * SS + t) * SPKD + (kg - 2048)];
        else if (kg < 2080) v = pos[((size_t)m * SS + t) * SPKD + (kg - 2064)];
        va[p] = v;
    }
#pragma unroll
    for (int p = 0; p < 16; p++) {
        int i = tid + p * 256;
        int n = i >> 4, kg = k0 + (i & 15);
        vw[p] = (kg < GINK) ? W[(size_t)(wrow + n) * GINK + kg] : 0.f;
    }

    for (int kt = k0; kt < k0 + 240; kt += 16) {
        __syncthreads();
#pragma unroll
        for (int p = 0; p < 4; p++) {
            int i = tid + p * 256;
            As[i & 15][i >> 4] = va[p];
        }
#pragma unroll
        for (int p = 0; p < 16; p++) {
            int i = tid + p * 256;
            Ws[i & 15][i >> 4] = vw[p];
        }
        __syncthreads();
        if (kt + 16 < k0 + 240) {
#pragma unroll
            for (int p = 0; p < 4; p++) {
                int i = tid + p * 256;
                int m = i >> 4, kg = kt + 16 + (i & 15);
                float v = 0.f;
                if (kg < 1024)      v = g_mem[((size_t)t * BB + m) * HH + kg];
                else if (kg < 2048) v = outp[((size_t)m * SS + (t - 1)) * HH + (kg - 1024)];
                else if (kg < 2064) v = spk[((size_t)m * SS + t) * SPKD + (kg - 2048)];
                else if (kg < 2080) v = pos[((size_t)m * SS + t) * SPKD + (kg - 2064)];
                va[p] = v;
            }
#pragma unroll
            for (int p = 0; p < 16; p++) {
                int i = tid + p * 256;
                int n = i >> 4, kg = kt + 16 + (i & 15);
                vw[p] = (kg < GINK) ? W[(size_t)(wrow + n) * GINK + kg] : 0.f;
            }
        }
        mk64(acc, (const float (*)[68])As, (const float (*)[260])Ws, tx, ty);
    }
#pragma unroll
    for (int i2 = 0; i2 < 8; i2++) {
        int m = ty * 8 + i2;
        size_t rowb = ((size_t)ks * BB + m) * 4096;
#pragma unroll
        for (int jp = 0; jp < 4; jp++) {
            int col = Nbase + 2 * tx + 64 * jp;
            F2U u; u.u = acc[i2][jp];
            *(float2*)&g_gpre[rowb + col] = u.f;
        }
    }
}

// ---------------- persistent gating kernel: 512 steps ----------------
__global__ __launch_bounds__(NTHR, 1) void gating_persistent(
    const float* __restrict__ spk, const float* __restrict__ pos,
    const float* __restrict__ Wfw, const float* __restrict__ bfb,
    const float* __restrict__ Wiw, const float* __restrict__ bib,
    const float* __restrict__ Wow, const float* __restrict__ bob,
    const float* __restrict__ Wcw, const float* __restrict__ bcb,
    const float* __restrict__ W1e, const float* __restrict__ b1e,
    const float* __restrict__ gln, const float* __restrict__ beta,
    const float* __restrict__ W2e, const float* __restrict__ b2e,
    float* __restrict__ out)
{
    __shared__ __align__(16) float As[16][68];
    __shared__ __align__(16) float Ws[16][260];
    __shared__ float sred[NTHR];
    __shared__ float stats[2];
    const int tid = threadIdx.x;
    const int tx = tid & 31, ty = tid >> 5;
    const int bx = blockIdx.x;
    unsigned int ep = *((volatile unsigned int*)&g_go);

    for (int t = 0; t < SS; t++) {
        if (t > 0) {
            gate_gemm(t, Wfw, Wiw, Wow, Wcw, out, spk, pos, As, Ws, tx, ty);
            gsync(ep);
            // gate combine -> g_gated
            for (int e = bx * NTHR + tid; e < BB * HH; e += NBLK * NTHR) {
                int b = e >> 10, i = e & 1023;
                float f = bfb[i], ig = bib[i], o = bob[i], c = bcb[i];
#pragma unroll
                for (int q = 0; q < KS_GATE; q++) {
                    size_t base = ((size_t)q * BB + b) * 4096;
                    f  += g_gpre[base + i];
                    ig += g_gpre[base + 1024 + i];
                    o  += g_gpre[base + 2048 + i];
                    c  += g_gpre[base + 3072 + i];
                }
                float prev = out[((size_t)b * SS + (t - 1)) * HH + i];
                f = sigm(f); ig = sigm(ig); o = sigm(o); c = tanhf(c);
                g_gated[e] = o * tanhf(f * prev + ig * c);
            }
            gsync(ep);
        }

        // emo GEMM1
        emo_gemm<0>(t, W1e, g_h1p, As, Ws, tx, ty);
        gsync(ep);

        // LayerNorm + ReLU (blocks 0..63)
        if (bx < BB) {
            const int b = bx;
            float v[4];
            float lsum = 0.f, lsq = 0.f;
#pragma unroll
            for (int j = 0; j < 4; j++) {
                int i = tid + j * NTHR;
                float x = b1e[i];
#pragma unroll
                for (int q = 0; q < KS_EMO; q++) x += g_h1p[((size_t)q * BB + b) * HH + i];
                v[j] = x; lsum += x; lsq += x * x;
            }
            sred[tid] = lsum; __syncthreads();
            for (int s2 = NTHR / 2; s2 > 0; s2 >>= 1) {
                if (tid < s2) sred[tid] += sred[tid + s2];
                __syncthreads();
            }
            if (tid == 0) stats[0] = sred[0] * (1.f / 1024.f);
            __syncthreads();
            sred[tid] = lsq; __syncthreads();
            for (int s2 = NTHR / 2; s2 > 0; s2 >>= 1) {
                if (tid < s2) sred[tid] += sred[tid + s2];
                __syncthreads();
            }
            if (tid == 0) stats[1] = sred[0] * (1.f / 1024.f);
            __syncthreads();
            float mu = stats[0];
            float var = stats[1] - mu * mu;
            float rs = rsqrtf(var + 1e-5f);
#pragma unroll
            for (int j = 0; j < 4; j++) {
                int i = tid + j * NTHR;
                float y = (v[j] - mu) * rs * gln[i] + beta[i];
                g_hln[(size_t)b * HH + i] = y > 0.f ? y : 0.f;
            }
        }
        gsync(ep);

        // emo GEMM2
        emo_gemm<1>(t, W2e, g_o2p, As, Ws, tx, ty);
        gsync(ep);

        // finalize out[t]
        for (int e = bx * NTHR + tid; e < BB * HH; e += NBLK * NTHR) {
            int b = e >> 10, i = e & 1023;
            float x = b2e[i];
#pragma unroll
            for (int q = 0; q < KS_EMO; q++) x += g_o2p[((size_t)q * BB + b) * HH + i];
            float res = (t == 0) ? g_mem[(size_t)b * HH + i] : g_gated[e];
            out[((size_t)b * SS + t) * HH + i] = x + res;
        }
        gsync(ep);
    }
}

// ---------------- host launcher: 3 graph nodes total ----------------
extern "C" void kernel_launch(void* const* d_in, const int* in_sizes, int n_in,
                              void* d_out, int out_size)
{
    (void)in_sizes; (void)n_in; (void)out_size;
    const float* uf    = (const float*)d_in[0];
    const float* spk   = (const float*)d_in[1];
    const float* pos   = (const float*)d_in[2];
    const float* Wih_f = (const float*)d_in[3];
    const float* Whh_f = (const float*)d_in[4];
    const float* bih_f = (const float*)d_in[5];
    const float* bhh_f = (const float*)d_in[6];
    const float* Wih_b = (const float*)d_in[7];
    const float* Whh_b = (const float*)d_in[8];
    const float* bih_b = (const float*)d_in[9];
    const float* bhh_b = (const float*)d_in[10];
    const float* Wfw   = (const float*)d_in[11];
    const float* bfb   = (const float*)d_in[12];
    const float* Wiw   = (const float*)d_in[13];
    const float* bib   = (const float*)d_in[14];
    const float* Wow   = (const float*)d_in[15];
    const float* bob   = (const float*)d_in[16];
    const float* Wcw   = (const float*)d_in[17];
    const float* bcb   = (const float*)d_in[18];
    const float* W1e   = (const float*)d_in[19];
    const float* b1e   = (const float*)d_in[20];
    const float* g_ln  = (const float*)d_in[21];
    const float* beta  = (const float*)d_in[22];
    const float* W2e   = (const float*)d_in[23];
    const float* b2e   = (const float*)d_in[24];
    float* out = (float*)d_out;

    // 1) x projections for both GRU directions (parallel, big grid)
    xproj_kernel<<<dim3(256, 12, 2), 256>>>(uf, Wih_f, bih_f, Wih_b, bih_b);

    // 2) persistent bidirectional GRU recurrence (two-level barrier)
    gru_persistent<<<NBLK, NTHR>>>(Whh_f, Whh_b, bhh_f, bhh_b);

    // 3) persistent dialogue gating loop (two-level barrier)
    gating_persistent<<<NBLK, NTHR>>>(spk, pos, Wfw, bfb, Wiw, bib, Wow, bob,
                                      Wcw, bcb, W1e, b1e, g_ln, beta, W2e, b2e, out);
}

// round 15
// speedup vs baseline: 1.3053x; 1.1080x over previous
#include <cuda_runtime.h>
#include <math.h>

#define BB 64
#define SS 512
#define DD 1024
#define HH 1024
#define HH2 512
#define G3 1536
#define GINK 2080
#define SPKD 16
#define NBLK 148
#define NTHR 256

typedef unsigned long long ull;
union F2U { ull u; float2 f; };

#define FMA2(d, a, b) \
    asm("fma.rn.f32x2 %0, %1, %2, %0;" : "+l"(d) : "l"(a), "l"(b))

__device__ __forceinline__ ull dup2(float a) {
    ull d;
    asm("mov.b64 %0, {%1, %1};" : "=l"(d) : "f"(a));
    return d;
}

// K-split counts (identical to the 37.0ms R7 kernel)
#define KS_GATE 9     // chunk 240 (15 tiles), K padded 2160
#define KS_GRU  11    // chunk 48 (3 tiles), last chunk 32
#define KS_EMO  32    // chunk 32 (2 tiles)

// ---------------- scratch (device globals; no allocation allowed) ----------------
static __device__ float g_xproj[(size_t)2 * SS * BB * G3];   // [dir][t][b][1536]
static __device__ float g_mem[(size_t)SS * BB * HH];          // [t][b][1024]
static __device__ float g_ghp[(size_t)KS_GRU * 2 * BB * G3];  // GRU gemm partials
static __device__ float g_gpre[(size_t)KS_GATE * BB * 4096];  // gate gemm partials
static __device__ float g_gated[(size_t)BB * HH];
static __device__ float g_h1p[(size_t)KS_EMO * BB * HH];      // emo gemm1 partials
static __device__ float g_hln[(size_t)BB * HH];
static __device__ float g_o2p[(size_t)KS_EMO * BB * HH];      // emo gemm2 partials
static __device__ unsigned int g_bar;

__global__ void reset_bar_k() { g_bar = 0u; }

// monotonic atomic grid barrier: all NBLK blocks co-resident (proven R7 design)
__device__ __forceinline__ void gsync(unsigned int& bar_id) {
    __syncthreads();
    if (threadIdx.x == 0) {
        __threadfence();
        atomicAdd(&g_bar, 1u);
        bar_id++;
        const unsigned int target = bar_id * NBLK;
        while (*((volatile unsigned int*)&g_bar) < target) {
            __nanosleep(20);
        }
        __threadfence();
    }
    __syncthreads();
}

__device__ __forceinline__ float sigm(float x) { return 1.f / (1.f + expf(-x)); }

// ---- M=64 x N=256 microkernel: 8m x 4 n-pairs per thread, broadcast-A ----
__device__ __forceinline__ void mk64(ull (&acc)[8][4],
                                     const float (*As)[68],
                                     const float (*Ws)[260],
                                     int tx, int ty) {
#pragma unroll
    for (int kk = 0; kk < 16; kk++) {
        float4 alo = *(const float4*)&As[kk][ty * 8];
        float4 ahi = *(const float4*)&As[kk][ty * 8 + 4];
        ull a2[8];
        a2[0] = dup2(alo.x); a2[1] = dup2(alo.y);
        a2[2] = dup2(alo.z); a2[3] = dup2(alo.w);
        a2[4] = dup2(ahi.x); a2[5] = dup2(ahi.y);
        a2[6] = dup2(ahi.z); a2[7] = dup2(ahi.w);
        ull b2[4];
#pragma unroll
        for (int jp = 0; jp < 4; jp++)
            b2[jp] = *(const ull*)&Ws[kk][2 * tx + 64 * jp];
#pragma unroll
        for (int i = 0; i < 8; i++)
#pragma unroll
            for (int jp = 0; jp < 4; jp++)
                FMA2(acc[i][jp], a2[i], b2[jp]);
    }
}

// ---------------- big GEMM: x_proj = x @ Wih.T + bih (both dirs; unchanged) ----------------
__global__ __launch_bounds__(256) void xproj_kernel(
    const float* __restrict__ uf,
    const float* __restrict__ Wf_, const float* __restrict__ bf_,
    const float* __restrict__ Wb_, const float* __restrict__ bb_)
{
    __shared__ __align__(16) float As[16][132];
    __shared__ __align__(16) float Ws[16][132];
    const int tid = threadIdx.x;
    const int tx = tid & 15, ty = tid >> 4;
    const int Mbase = blockIdx.x * 128;
    const int Nbase = blockIdx.y * 128;
    const int dir = blockIdx.z;
    const float* W = dir ? Wb_ : Wf_;
    const float* bias = dir ? bb_ : bf_;

    const float* ap[8];
    const float* wp[8];
#pragma unroll
    for (int p = 0; p < 8; p++) {
        int i = tid + p * 256;
        int m = i >> 4, k = i & 15;
        int mg = Mbase + m;
        int tt = mg >> 6, b = mg & 63;
        int srow = dir ? (SS - 1 - tt) : tt;
        ap[p] = uf + ((size_t)b * SS + srow) * DD + k;
        wp[p] = W + (size_t)(Nbase + m) * DD + k;
    }

    ull acc[8][4];
#pragma unroll
    for (int i = 0; i < 8; i++)
#pragma unroll
        for (int j = 0; j < 4; j++) acc[i][j] = 0ull;

    float va[8], vw[8];
#pragma unroll
    for (int p = 0; p < 8; p++) { va[p] = ap[p][0]; vw[p] = wp[p][0]; }

    for (int kt = 0; kt < DD; kt += 16) {
        __syncthreads();
#pragma unroll
        for (int p = 0; p < 8; p++) {
            int i = tid + p * 256;
            As[i & 15][i >> 4] = va[p];
            Ws[i & 15][i >> 4] = vw[p];
        }
        __syncthreads();
        if (kt + 16 < DD) {
#pragma unroll
            for (int p = 0; p < 8; p++) {
                va[p] = ap[p][kt + 16];
                vw[p] = wp[p][kt + 16];
            }
        }
#pragma unroll
        for (int kk = 0; kk < 16; kk++) {
            float4 alo = *(const float4*)&As[kk][ty * 8];
            float4 ahi = *(const float4*)&As[kk][ty * 8 + 4];
            ull a2[8];
            a2[0] = dup2(alo.x); a2[1] = dup2(alo.y);
            a2[2] = dup2(alo.z); a2[3] = dup2(alo.w);
            a2[4] = dup2(ahi.x); a2[5] = dup2(ahi.y);
            a2[6] = dup2(ahi.z); a2[7] = dup2(ahi.w);
            ull b2[4];
#pragma unroll
            for (int jp = 0; jp < 4; jp++)
                b2[jp] = *(const ull*)&Ws[kk][2 * tx + 32 * jp];
#pragma unroll
            for (int i = 0; i < 8; i++)
#pragma unroll
                for (int jp = 0; jp < 4; jp++)
                    FMA2(acc[i][jp], a2[i], b2[jp]);
        }
    }

#pragma unroll
    for (int i = 0; i < 8; i++) {
        int mg = Mbase + ty * 8 + i;
        size_t rowb = ((size_t)dir * SS * BB + mg) * G3;
#pragma unroll
        for (int jp = 0; jp < 4; jp++) {
            int col = Nbase + 2 * tx + 32 * jp;
            F2U u; u.u = acc[i][jp];
            u.f.x += bias[col];
            u.f.y += bias[col + 1];
            *(float2*)&g_xproj[rowb + col] = u.f;
        }
    }
}

// ---------------- persistent GRU: 512 steps, double-buffered GEMM ----------------
__global__ __launch_bounds__(NTHR, 1) void gru_persistent(
    const float* __restrict__ Whh_f, const float* __restrict__ Whh_b,
    const float* __restrict__ bhh_f, const float* __restrict__ bhh_b)
{
    __shared__ __align__(16) float As[2][16][68];
    __shared__ __align__(16) float Ws[2][16][260];
    const int tid = threadIdx.x;
    const int tx = tid & 31, ty = tid >> 5;
    const int bx = blockIdx.x;
    unsigned int bar_id = 0;

    const int w = bx;
    const bool active = (w < 2 * 6 * KS_GRU);
    const int dir = w / (6 * KS_GRU);
    const int rem = w % (6 * KS_GRU);
    const int nt = rem / KS_GRU;
    const int ks = rem % KS_GRU;
    const float* W = dir ? Whh_b : Whh_f;
    const int Nbase = nt * 256;
    const int k0 = ks * 48;
    const int k1 = (k0 + 48 < HH2) ? (k0 + 48) : HH2;
    const int ntile = (k1 - k0) >> 4;

    for (int t = 0; t < SS; t++) {
        if (active) {
            ull acc[8][4];
#pragma unroll
            for (int i = 0; i < 8; i++)
#pragma unroll
                for (int j = 0; j < 4; j++) acc[i][j] = 0ull;

            float va[4], vw[16];
            // prologue: load tile 0, store buf 0
#pragma unroll
            for (int p = 0; p < 4; p++) {
                int i = tid + p * 256;
                int m = i >> 4, kg = k0 + (i & 15);
                float v = 0.f;
                if (t > 0)
                    v = dir ? g_mem[((size_t)(SS - t) * BB + m) * HH + HH2 + kg]
                            : g_mem[((size_t)(t - 1) * BB + m) * HH + kg];
                va[p] = v;
            }
#pragma unroll
            for (int p = 0; p < 16; p++) {
                int i = tid + p * 256;
                int n = i >> 4, kg = k0 + (i & 15);
                vw[p] = W[(size_t)(Nbase + n) * HH2 + kg];
            }
#pragma unroll
            for (int p = 0; p < 4; p++) {
                int i = tid + p * 256;
                As[0][i & 15][i >> 4] = va[p];
            }
#pragma unroll
            for (int p = 0; p < 16; p++) {
                int i = tid + p * 256;
                Ws[0][i & 15][i >> 4] = vw[p];
            }
            __syncthreads();

            for (int it = 0; it < ntile; it++) {
                const bool more = (it + 1 < ntile);
                if (more) {
                    int kg0 = k0 + (it + 1) * 16;
#pragma unroll
                    for (int p = 0; p < 4; p++) {
                        int i = tid + p * 256;
                        int m = i >> 4, kg = kg0 + (i & 15);
                        float v = 0.f;
                        if (t > 0)
                            v = dir ? g_mem[((size_t)(SS - t) * BB + m) * HH + HH2 + kg]
                                    : g_mem[((size_t)(t - 1) * BB + m) * HH + kg];
                        va[p] = v;
                    }
#pragma unroll
                    for (int p = 0; p < 16; p++) {
                        int i = tid + p * 256;
                        int n = i >> 4, kg = kg0 + (i & 15);
                        vw[p] = W[(size_t)(Nbase + n) * HH2 + kg];
                    }
                }
                mk64(acc, As[it & 1], Ws[it & 1], tx, ty);
                if (more) {
#pragma unroll
                    for (int p = 0; p < 4; p++) {
                        int i = tid + p * 256;
                        As[(it + 1) & 1][i & 15][i >> 4] = va[p];
                    }
#pragma unroll
                    for (int p = 0; p < 16; p++) {
                        int i = tid + p * 256;
                        Ws[(it + 1) & 1][i & 15][i >> 4] = vw[p];
                    }
                    __syncthreads();
                }
            }
#pragma unroll
            for (int i2 = 0; i2 < 8; i2++) {
                int m = ty * 8 + i2;
                size_t rowb = (((size_t)ks * 2 + dir) * BB + m) * G3;
#pragma unroll
                for (int jp = 0; jp < 4; jp++) {
                    int col = Nbase + 2 * tx + 64 * jp;
                    F2U u; u.u = acc[i2][jp];
                    *(float2*)&g_ghp[rowb + col] = u.f;
                }
            }
        }
        gsync(bar_id);

        // combine: 2*64*512 = 65536 elems
        for (int e = bx * NTHR + tid; e < 2 * BB * HH2; e += NBLK * NTHR) {
            int d2 = e >> 15;
            int b = (e >> 9) & 63;
            int i = e & 511;
            const float* bhh = d2 ? bhh_b : bhh_f;
            float hr = bhh[i], hz = bhh[HH2 + i], hn = bhh[2 * HH2 + i];
#pragma unroll
            for (int q = 0; q < KS_GRU; q++) {
                size_t base = (((size_t)q * 2 + d2) * BB + b) * G3;
                hr += g_ghp[base + i];
                hz += g_ghp[base + HH2 + i];
                hn += g_ghp[base + 2 * HH2 + i];
            }
            size_t xb = (((size_t)d2 * SS + t) * BB + b) * G3;
            float xr = g_xproj[xb + i], xz = g_xproj[xb + HH2 + i], xn = g_xproj[xb + 2 * HH2 + i];
            float hp = 0.f;
            if (t > 0)
                hp = d2 ? g_mem[((size_t)(SS - t) * BB + b) * HH + HH2 + i]
                        : g_mem[((size_t)(t - 1) * BB + b) * HH + i];
            float r = sigm(xr + hr);
            float z = sigm(xz + hz);
            float n2 = tanhf(xn + r * hn);
            float h = (1.f - z) * n2 + z * hp;
            if (d2 == 0) g_mem[((size_t)t * BB + b) * HH + i] = h;
            else         g_mem[((size_t)(SS - 1 - t) * BB + b) * HH + HH2 + i] = h;
        }
        gsync(bar_id);
    }
}

// ---------------- emo GEMM phase: double-buffered, N=1024 (4x256), K=1024 (32x32) ----------------
template <int AMODE>
__device__ __forceinline__ void emo_gemm(int t, const float* __restrict__ W,
                                         float* __restrict__ dst,
                                         float (*As)[16][68], float (*Ws)[16][260],
                                         int tx, int ty)
{
    const int tid = threadIdx.x;
    const int w = blockIdx.x;
    if (w >= 4 * KS_EMO) return;
    const int nt = w >> 5;
    const int ks = w & 31;
    const int Nbase = nt * 256;
    const int k0 = ks * 32;

    ull acc[8][4];
#pragma unroll
    for (int i = 0; i < 8; i++)
#pragma unroll
        for (int j = 0; j < 4; j++) acc[i][j] = 0ull;

    float va[4], vw[16];
#pragma unroll
    for (int p = 0; p < 4; p++) {
        int i = tid + p * 256;
        int m = i >> 4, kg = k0 + (i & 15);
        float v;
        if (AMODE == 0)
            v = (t == 0) ? g_mem[(size_t)m * HH + kg] : g_gated[(size_t)m * HH + kg];
        else
            v = g_hln[(size_t)m * HH + kg];
        va[p] = v;
    }
#pragma unroll
    for (int p = 0; p < 16; p++) {
        int i = tid + p * 256;
        int n = i >> 4, kg = k0 + (i & 15);
        vw[p] = W[(size_t)(Nbase + n) * HH + kg];
    }
#pragma unroll
    for (int p = 0; p < 4; p++) {
        int i = tid + p * 256;
        As[0][i & 15][i >> 4] = va[p];
    }
#pragma unroll
    for (int p = 0; p < 16; p++) {
        int i = tid + p * 256;
        Ws[0][i & 15][i >> 4] = vw[p];
    }
    __syncthreads();

#pragma unroll
    for (int it = 0; it < 2; it++) {
        if (it == 0) {
#pragma unroll
            for (int p = 0; p < 4; p++) {
                int i = tid + p * 256;
                int m = i >> 4, kg = k0 + 16 + (i & 15);
                float v;
                if (AMODE == 0)
                    v = (t == 0) ? g_mem[(size_t)m * HH + kg] : g_gated[(size_t)m * HH + kg];
                else
                    v = g_hln[(size_t)m * HH + kg];
                va[p] = v;
            }
#pragma unroll
            for (int p = 0; p < 16; p++) {
                int i = tid + p * 256;
                int n = i >> 4, kg = k0 + 16 + (i & 15);
                vw[p] = W[(size_t)(Nbase + n) * HH + kg];
            }
        }
        mk64(acc, (const float (*)[68])As[it & 1], (const float (*)[260])Ws[it & 1], tx, ty);
        if (it == 0) {
#pragma unroll
            for (int p = 0; p < 4; p++) {
                int i = tid + p * 256;
                As[1][i & 15][i >> 4] = va[p];
            }
#pragma unroll
            for (int p = 0; p < 16; p++) {
                int i = tid + p * 256;
                Ws[1][i & 15][i >> 4] = vw[p];
            }
            __syncthreads();
        }
    }
#pragma unroll
    for (int i2 = 0; i2 < 8; i2++) {
        int m = ty * 8 + i2;
        size_t rowb = ((size_t)ks * BB + m) * HH;
#pragma unroll
        for (int jp = 0; jp < 4; jp++) {
            int col = Nbase + 2 * tx + 64 * jp;
            F2U u; u.u = acc[i2][jp];
            *(float2*)&dst[rowb + col] = u.f;
        }
    }
}

// ---------------- gate GEMM phase: double-buffered, N=4096 (16x256), K pad 2160 (9x240) ----------------
__device__ __forceinline__ void gate_gemm(int t,
    const float* __restrict__ Wf, const float* __restrict__ Wi,
    const float* __restrict__ Wo, const float* __restrict__ Wc,
    const float* __restrict__ outp, const float* __restrict__ spk,
    const float* __restrict__ pos,
    float (*As)[16][68], float (*Ws)[16][260], int tx, int ty)
{
    const int tid = threadIdx.x;
    const int w = blockIdx.x;
    if (w >= 16 * KS_GATE) return;
    const int nt = w / KS_GATE;
    const int ks = w % KS_GATE;
    const int Nbase = nt * 256;
    const int gate = Nbase >> 10;
    const float* W = (gate == 0) ? Wf : (gate == 1) ? Wi : (gate == 2) ? Wo : Wc;
    const int wrow = Nbase & 1023;
    const int k0 = ks * 240;

    ull acc[8][4];
#pragma unroll
    for (int i = 0; i < 8; i++)
#pragma unroll
        for (int j = 0; j < 4; j++) acc[i][j] = 0ull;

    float va[4], vw[16];
#pragma unroll
    for (int p = 0; p < 4; p++) {
        int i = tid + p * 256;
        int m = i >> 4, kg = k0 + (i & 15);
        float v = 0.f;
        if (kg < 1024)      v = g_mem[((size_t)t * BB + m) * HH + kg];
        else if (kg < 2048) v = outp[((size_t)m * SS + (t - 1)) * HH + (kg - 1024)];
        else if (kg < 2064) v = spk[((size_t)m * SS + t) * SPKD + (kg - 2048)];
        else if (kg < 2080) v = pos[((size_t)m * SS + t) * SPKD + (kg - 2064)];
        va[p] = v;
    }
#pragma unroll
    for (int p = 0; p < 16; p++) {
        int i = tid + p * 256;
        int n = i >> 4, kg = k0 + (i & 15);
        vw[p] = (kg < GINK) ? W[(size_t)(wrow + n) * GINK + kg] : 0.f;
    }
#pragma unroll
    for (int p = 0; p < 4; p++) {
        int i = tid + p * 256;
        As[0][i & 15][i >> 4] = va[p];
    }
#pragma unroll
    for (int p = 0; p < 16; p++) {
        int i = tid + p * 256;
        Ws[0][i & 15][i >> 4] = vw[p];
    }
    __syncthreads();

    for (int it = 0; it < 15; it++) {
        const bool more = (it + 1 < 15);
        if (more) {
            int kg0 = k0 + (it + 1) * 16;
#pragma unroll
            for (int p = 0; p < 4; p++) {
                int i = tid + p * 256;
                int m = i >> 4, kg = kg0 + (i & 15);
                float v = 0.f;
                if (kg < 1024)      v = g_mem[((size_t)t * BB + m) * HH + kg];
                else if (kg < 2048) v = outp[((size_t)m * SS + (t - 1)) * HH + (kg - 1024)];
                else if (kg < 2064) v = spk[((size_t)m * SS + t) * SPKD + (kg - 2048)];
                else if (kg < 2080) v = pos[((size_t)m * SS + t) * SPKD + (kg - 2064)];
                va[p] = v;
            }
#pragma unroll
            for (int p = 0; p < 16; p++) {
                int i = tid + p * 256;
                int n = i >> 4, kg = kg0 + (i & 15);
                vw[p] = (kg < GINK) ? W[(size_t)(wrow + n) * GINK + kg] : 0.f;
            }
        }
        mk64(acc, (const float (*)[68])As[it & 1], (const float (*)[260])Ws[it & 1], tx, ty);
        if (more) {
#pragma unroll
            for (int p = 0; p < 4; p++) {
                int i = tid + p * 256;
                As[(it + 1) & 1][i & 15][i >> 4] = va[p];
            }
#pragma unroll
            for (int p = 0; p < 16; p++) {
                int i = tid + p * 256;
                Ws[(it + 1) & 1][i & 15][i >> 4] = vw[p];
            }
            __syncthreads();
        }
    }
#pragma unroll
    for (int i2 = 0; i2 < 8; i2++) {
        int m = ty * 8 + i2;
        size_t rowb = ((size_t)ks * BB + m) * 4096;
#pragma unroll
        for (int jp = 0; jp < 4; jp++) {
            int col = Nbase + 2 * tx + 64 * jp;
            F2U u; u.u = acc[i2][jp];
            *(float2*)&g_gpre[rowb + col] = u.f;
        }
    }
}

// ---------------- persistent gating kernel: 512 steps ----------------
__global__ __launch_bounds__(NTHR, 1) void gating_persistent(
    const float* __restrict__ spk, const float* __restrict__ pos,
    const float* __restrict__ Wfw, const float* __restrict__ bfb,
    const float* __restrict__ Wiw, const float* __restrict__ bib,
    const float* __restrict__ Wow, const float* __restrict__ bob,
    const float* __restrict__ Wcw, const float* __restrict__ bcb,
    const float* __restrict__ W1e, const float* __restrict__ b1e,
    const float* __restrict__ gln, const float* __restrict__ beta,
    const float* __restrict__ W2e, const float* __restrict__ b2e,
    float* __restrict__ out)
{
    __shared__ __align__(16) float As[2][16][68];
    __shared__ __align__(16) float Ws[2][16][260];
    __shared__ float sred[NTHR];
    __shared__ float stats[2];
    const int tid = threadIdx.x;
    const int tx = tid & 31, ty = tid >> 5;
    const int bx = blockIdx.x;
    unsigned int bar_id = 0;

    for (int t = 0; t < SS; t++) {
        if (t > 0) {
            gate_gemm(t, Wfw, Wiw, Wow, Wcw, out, spk, pos, As, Ws, tx, ty);
            gsync(bar_id);
            // gate combine -> g_gated
            for (int e = bx * NTHR + tid; e < BB * HH; e += NBLK * NTHR) {
                int b = e >> 10, i = e & 1023;
                float f = bfb[i], ig = bib[i], o = bob[i], c = bcb[i];
#pragma unroll
                for (int q = 0; q < KS_GATE; q++) {
                    size_t base = ((size_t)q * BB + b) * 4096;
                    f  += g_gpre[base + i];
                    ig += g_gpre[base + 1024 + i];
                    o  += g_gpre[base + 2048 + i];
                    c  += g_gpre[base + 3072 + i];
                }
                float prev = out[((size_t)b * SS + (t - 1)) * HH + i];
                f = sigm(f); ig = sigm(ig); o = sigm(o); c = tanhf(c);
                g_gated[e] = o * tanhf(f * prev + ig * c);
            }
            gsync(bar_id);
        }

        // emo GEMM1
        emo_gemm<0>(t, W1e, g_h1p, As, Ws, tx, ty);
        gsync(bar_id);

        // LayerNorm + ReLU (blocks 0..63)
        if (bx < BB) {
            const int b = bx;
            float v[4];
            float lsum = 0.f, lsq = 0.f;
#pragma unroll
            for (int j = 0; j < 4; j++) {
                int i = tid + j * NTHR;
                float x = b1e[i];
#pragma unroll
                for (int q = 0; q < KS_EMO; q++) x += g_h1p[((size_t)q * BB + b) * HH + i];
                v[j] = x; lsum += x; lsq += x * x;
            }
            sred[tid] = lsum; __syncthreads();
            for (int s2 = NTHR / 2; s2 > 0; s2 >>= 1) {
                if (tid < s2) sred[tid] += sred[tid + s2];
                __syncthreads();
            }
            if (tid == 0) stats[0] = sred[0] * (1.f / 1024.f);
            __syncthreads();
            sred[tid] = lsq; __syncthreads();
            for (int s2 = NTHR / 2; s2 > 0; s2 >>= 1) {
                if (tid < s2) sred[tid] += sred[tid + s2];
                __syncthreads();
            }
            if (tid == 0) stats[1] = sred[0] * (1.f / 1024.f);
            __syncthreads();
            float mu = stats[0];
            float var = stats[1] - mu * mu;
            float rs = rsqrtf(var + 1e-5f);
#pragma unroll
            for (int j = 0; j < 4; j++) {
                int i = tid + j * NTHR;
                float y = (v[j] - mu) * rs * gln[i] + beta[i];
                g_hln[(size_t)b * HH + i] = y > 0.f ? y : 0.f;
            }
        }
        gsync(bar_id);

        // emo GEMM2
        emo_gemm<1>(t, W2e, g_o2p, As, Ws, tx, ty);
        gsync(bar_id);

        // finalize out[t]
        for (int e = bx * NTHR + tid; e < BB * HH; e += NBLK * NTHR) {
            int b = e >> 10, i = e & 1023;
            float x = b2e[i];
#pragma unroll
            for (int q = 0; q < KS_EMO; q++) x += g_o2p[((size_t)q * BB + b) * HH + i];
            float res = (t == 0) ? g_mem[(size_t)b * HH + i] : g_gated[e];
            out[((size_t)b * SS + t) * HH + i] = x + res;
        }
        gsync(bar_id);
    }
}

// ---------------- host launcher: 5 graph nodes total ----------------
extern "C" void kernel_launch(void* const* d_in, const int* in_sizes, int n_in,
                              void* d_out, int out_size)
{
    (void)in_sizes; (void)n_in; (void)out_size;
    const float* uf    = (const float*)d_in[0];
    const float* spk   = (const float*)d_in[1];
    const float* pos   = (const float*)d_in[2];
    const float* Wih_f = (const float*)d_in[3];
    const float* Whh_f = (const float*)d_in[4];
    const float* bih_f = (const float*)d_in[5];
    const float* bhh_f = (const float*)d_in[6];
    const float* Wih_b = (const float*)d_in[7];
    const float* Whh_b = (const float*)d_in[8];
    const float* bih_b = (const float*)d_in[9];
    const float* bhh_b = (const float*)d_in[10];
    const float* Wfw   = (const float*)d_in[11];
    const float* bfb   = (const float*)d_in[12];
    const float* Wiw   = (const float*)d_in[13];
    const float* bib   = (const float*)d_in[14];
    const float* Wow   = (const float*)d_in[15];
    const float* bob   = (const float*)d_in[16];
    const float* Wcw   = (const float*)d_in[17];
    const float* bcb   = (const float*)d_in[18];
    const float* W1e   = (const float*)d_in[19];
    const float* b1e   = (const float*)d_in[20];
    const float* g_ln  = (const float*)d_in[21];
    const float* beta  = (const float*)d_in[22];
    const float* W2e   = (const float*)d_in[23];
    const float* b2e   = (const float*)d_in[24];
    float* out = (float*)d_out;

    // 1) x projections for both GRU directions (parallel, big grid)
    xproj_kernel<<<dim3(256, 12, 2), 256>>>(uf, Wih_f, bih_f, Wih_b, bih_b);

    // 2) persistent bidirectional GRU recurrence (double-buffered GEMM)
    reset_bar_k<<<1, 1>>>();
    gru_persistent<<<NBLK, NTHR>>>(Whh_f, Whh_b, bhh_f, bhh_b);

    // 3) persistent dialogue gating loop (double-buffered GEMMs)
    reset_bar_k<<<1, 1>>>();
    gating_persistent<<<NBLK, NTHR>>>(spk, pos, Wfw, bfb, Wiw, bib, Wow, bob,
                                      Wcw, bcb, W1e, b1e, g_ln, beta, W2e, b2e, out);
}

// round 16
// speedup vs baseline: 1.3495x; 1.0339x over previous
#include <cuda_runtime.h>
#include <math.h>

#define BB 64
#define SS 512
#define DD 1024
#define HH 1024
#define HH2 512
#define G3 1536
#define GINK 2080
#define SPKD 16
#define NBLK 148
#define NTHR 256

typedef unsigned long long ull;
union F2U { ull u; float2 f; };

#define FMA2(d, a, b) \
    asm("fma.rn.f32x2 %0, %1, %2, %0;" : "+l"(d) : "l"(a), "l"(b))

__device__ __forceinline__ ull dup2(float a) {
    ull d;
    asm("mov.b64 %0, {%1, %1};" : "=l"(d) : "f"(a));
    return d;
}

// K-split counts
#define KS_GATE 9     // chunk 240 (15 tiles), K padded 2160
#define KS_GRU  11    // chunk 48 (3 tiles), last chunk 32
#define KS_EMO  16    // N=128 tiles, chunk 64 (4 tiles)

// ---------------- scratch (device globals; no allocation allowed) ----------------
static __device__ float g_xproj[(size_t)2 * SS * BB * G3];   // [dir][t][b][1536]
static __device__ float g_mem[(size_t)SS * BB * HH];          // [t][b][1024]
static __device__ float g_ghp[(size_t)KS_GRU * 2 * BB * G3];  // GRU gemm partials
static __device__ float g_gpre[(size_t)KS_GATE * BB * 4096];  // gate gemm partials
static __device__ float g_gated[(size_t)BB * HH];
static __device__ float g_h1p[(size_t)KS_EMO * BB * HH];      // emo gemm1 partials
static __device__ float g_hln[(size_t)BB * HH];
static __device__ float g_o2p[(size_t)KS_EMO * BB * HH];      // emo gemm2 partials
static __device__ unsigned int g_bar;

__global__ void reset_bar_k() { g_bar = 0u; }

// monotonic atomic grid barrier: all NBLK blocks co-resident
__device__ __forceinline__ void gsync(unsigned int& bar_id) {
    __syncthreads();
    if (threadIdx.x == 0) {
        __threadfence();
        atomicAdd(&g_bar, 1u);
        bar_id++;
        const unsigned int target = bar_id * NBLK;
        while (*((volatile unsigned int*)&g_bar) < target) {
            __nanosleep(20);
        }
        __threadfence();
    }
    __syncthreads();
}

__device__ __forceinline__ float sigm(float x) { return 1.f / (1.f + expf(-x)); }

// ---- M=64 x N=256 microkernel: 8m x 4 n-pairs per thread, broadcast-A ----
__device__ __forceinline__ void mk64(ull (&acc)[8][4],
                                     const float (*As)[68],
                                     const float (*Ws)[260],
                                     int tx, int ty) {
#pragma unroll
    for (int kk = 0; kk < 16; kk++) {
        float4 alo = *(const float4*)&As[kk][ty * 8];
        float4 ahi = *(const float4*)&As[kk][ty * 8 + 4];
        ull a2[8];
        a2[0] = dup2(alo.x); a2[1] = dup2(alo.y);
        a2[2] = dup2(alo.z); a2[3] = dup2(alo.w);
        a2[4] = dup2(ahi.x); a2[5] = dup2(ahi.y);
        a2[6] = dup2(ahi.z); a2[7] = dup2(ahi.w);
        ull b2[4];
#pragma unroll
        for (int jp = 0; jp < 4; jp++)
            b2[jp] = *(const ull*)&Ws[kk][2 * tx + 64 * jp];
#pragma unroll
        for (int i = 0; i < 8; i++)
#pragma unroll
            for (int jp = 0; jp < 4; jp++)
                FMA2(acc[i][jp], a2[i], b2[jp]);
    }
}

// ---- M=64 x N=128 microkernel: 4m x 4 n-pairs (tx=tid&15, ty=tid>>4) ----
__device__ __forceinline__ void mk128(ull (&acc)[4][4],
                                      const float (*As)[68],
                                      const float (*Ws)[260],
                                      int tx, int ty) {
#pragma unroll
    for (int kk = 0; kk < 16; kk++) {
        float4 av = *(const float4*)&As[kk][ty * 4];
        ull a2[4];
        a2[0] = dup2(av.x); a2[1] = dup2(av.y);
        a2[2] = dup2(av.z); a2[3] = dup2(av.w);
        ull b2[4];
#pragma unroll
        for (int jp = 0; jp < 4; jp++)
            b2[jp] = *(const ull*)&Ws[kk][2 * tx + 32 * jp];
#pragma unroll
        for (int i = 0; i < 4; i++)
#pragma unroll
            for (int jp = 0; jp < 4; jp++)
                FMA2(acc[i][jp], a2[i], b2[jp]);
    }
}

// ---------------- big GEMM: x_proj = x @ Wih.T + bih (both dirs; unchanged) ----------------
__global__ __launch_bounds__(256) void xproj_kernel(
    const float* __restrict__ uf,
    const float* __restrict__ Wf_, const float* __restrict__ bf_,
    const float* __restrict__ Wb_, const float* __restrict__ bb_)
{
    __shared__ __align__(16) float As[16][132];
    __shared__ __align__(16) float Ws[16][132];
    const int tid = threadIdx.x;
    const int tx = tid & 15, ty = tid >> 4;
    const int Mbase = blockIdx.x * 128;
    const int Nbase = blockIdx.y * 128;
    const int dir = blockIdx.z;
    const float* W = dir ? Wb_ : Wf_;
    const float* bias = dir ? bb_ : bf_;

    const float* ap[8];
    const float* wp[8];
#pragma unroll
    for (int p = 0; p < 8; p++) {
        int i = tid + p * 256;
        int m = i >> 4, k = i & 15;
        int mg = Mbase + m;
        int tt = mg >> 6, b = mg & 63;
        int srow = dir ? (SS - 1 - tt) : tt;
        ap[p] = uf + ((size_t)b * SS + srow) * DD + k;
        wp[p] = W + (size_t)(Nbase + m) * DD + k;
    }

    ull acc[8][4];
#pragma unroll
    for (int i = 0; i < 8; i++)
#pragma unroll
        for (int j = 0; j < 4; j++) acc[i][j] = 0ull;

    float va[8], vw[8];
#pragma unroll
    for (int p = 0; p < 8; p++) { va[p] = ap[p][0]; vw[p] = wp[p][0]; }

    for (int kt = 0; kt < DD; kt += 16) {
        __syncthreads();
#pragma unroll
        for (int p = 0; p < 8; p++) {
            int i = tid + p * 256;
            As[i & 15][i >> 4] = va[p];
            Ws[i & 15][i >> 4] = vw[p];
        }
        __syncthreads();
        if (kt + 16 < DD) {
#pragma unroll
            for (int p = 0; p < 8; p++) {
                va[p] = ap[p][kt + 16];
                vw[p] = wp[p][kt + 16];
            }
        }
#pragma unroll
        for (int kk = 0; kk < 16; kk++) {
            float4 alo = *(const float4*)&As[kk][ty * 8];
            float4 ahi = *(const float4*)&As[kk][ty * 8 + 4];
            ull a2[8];
            a2[0] = dup2(alo.x); a2[1] = dup2(alo.y);
            a2[2] = dup2(alo.z); a2[3] = dup2(alo.w);
            a2[4] = dup2(ahi.x); a2[5] = dup2(ahi.y);
            a2[6] = dup2(ahi.z); a2[7] = dup2(ahi.w);
            ull b2[4];
#pragma unroll
            for (int jp = 0; jp < 4; jp++)
                b2[jp] = *(const ull*)&Ws[kk][2 * tx + 32 * jp];
#pragma unroll
            for (int i = 0; i < 8; i++)
#pragma unroll
                for (int jp = 0; jp < 4; jp++)
                    FMA2(acc[i][jp], a2[i], b2[jp]);
        }
    }

#pragma unroll
    for (int i = 0; i < 8; i++) {
        int mg = Mbase + ty * 8 + i;
        size_t rowb = ((size_t)dir * SS * BB + mg) * G3;
#pragma unroll
        for (int jp = 0; jp < 4; jp++) {
            int col = Nbase + 2 * tx + 32 * jp;
            F2U u; u.u = acc[i][jp];
            u.f.x += bias[col];
            u.f.y += bias[col + 1];
            *(float2*)&g_xproj[rowb + col] = u.f;
        }
    }
}

// ---------------- persistent GRU: 512 steps, double-buffered GEMM ----------------
__global__ __launch_bounds__(NTHR, 1) void gru_persistent(
    const float* __restrict__ Whh_f, const float* __restrict__ Whh_b,
    const float* __restrict__ bhh_f, const float* __restrict__ bhh_b)
{
    __shared__ __align__(16) float As[2][16][68];
    __shared__ __align__(16) float Ws[2][16][260];
    const int tid = threadIdx.x;
    const int tx = tid & 31, ty = tid >> 5;
    const int bx = blockIdx.x;
    unsigned int bar_id = 0;

    const int w = bx;
    const bool active = (w < 2 * 6 * KS_GRU);
    const int dir = w / (6 * KS_GRU);
    const int rem = w % (6 * KS_GRU);
    const int nt = rem / KS_GRU;
    const int ks = rem % KS_GRU;
    const float* W = dir ? Whh_b : Whh_f;
    const int Nbase = nt * 256;
    const int k0 = ks * 48;
    const int k1 = (k0 + 48 < HH2) ? (k0 + 48) : HH2;
    const int ntile = (k1 - k0) >> 4;

    for (int t = 0; t < SS; t++) {
        if (active) {
            ull acc[8][4];
#pragma unroll
            for (int i = 0; i < 8; i++)
#pragma unroll
                for (int j = 0; j < 4; j++) acc[i][j] = 0ull;

            float va[4], vw[16];
#pragma unroll
            for (int p = 0; p < 4; p++) {
                int i = tid + p * 256;
                int m = i >> 4, kg = k0 + (i & 15);
                float v = 0.f;
                if (t > 0)
                    v = dir ? g_mem[((size_t)(SS - t) * BB + m) * HH + HH2 + kg]
                            : g_mem[((size_t)(t - 1) * BB + m) * HH + kg];
                va[p] = v;
            }
#pragma unroll
            for (int p = 0; p < 16; p++) {
                int i = tid + p * 256;
                int n = i >> 4, kg = k0 + (i & 15);
                vw[p] = W[(size_t)(Nbase + n) * HH2 + kg];
            }
#pragma unroll
            for (int p = 0; p < 4; p++) {
                int i = tid + p * 256;
                As[0][i & 15][i >> 4] = va[p];
            }
#pragma unroll
            for (int p = 0; p < 16; p++) {
                int i = tid + p * 256;
                Ws[0][i & 15][i >> 4] = vw[p];
            }
            __syncthreads();

            for (int it = 0; it < ntile; it++) {
                const bool more = (it + 1 < ntile);
                if (more) {
                    int kg0 = k0 + (it + 1) * 16;
#pragma unroll
                    for (int p = 0; p < 4; p++) {
                        int i = tid + p * 256;
                        int m = i >> 4, kg = kg0 + (i & 15);
                        float v = 0.f;
                        if (t > 0)
                            v = dir ? g_mem[((size_t)(SS - t) * BB + m) * HH + HH2 + kg]
                                    : g_mem[((size_t)(t - 1) * BB + m) * HH + kg];
                        va[p] = v;
                    }
#pragma unroll
                    for (int p = 0; p < 16; p++) {
                        int i = tid + p * 256;
                        int n = i >> 4, kg = kg0 + (i & 15);
                        vw[p] = W[(size_t)(Nbase + n) * HH2 + kg];
                    }
                }
                mk64(acc, As[it & 1], Ws[it & 1], tx, ty);
                if (more) {
#pragma unroll
                    for (int p = 0; p < 4; p++) {
                        int i = tid + p * 256;
                        As[(it + 1) & 1][i & 15][i >> 4] = va[p];
                    }
#pragma unroll
                    for (int p = 0; p < 16; p++) {
                        int i = tid + p * 256;
                        Ws[(it + 1) & 1][i & 15][i >> 4] = vw[p];
                    }
                    __syncthreads();
                }
            }
#pragma unroll
            for (int i2 = 0; i2 < 8; i2++) {
                int m = ty * 8 + i2;
                size_t rowb = (((size_t)ks * 2 + dir) * BB + m) * G3;
#pragma unroll
                for (int jp = 0; jp < 4; jp++) {
                    int col = Nbase + 2 * tx + 64 * jp;
                    F2U u; u.u = acc[i2][jp];
                    *(float2*)&g_ghp[rowb + col] = u.f;
                }
            }
        }
        gsync(bar_id);

        // combine (float2): 2*64*512 = 65536 elems -> 32768 pairs, single pass
        for (int e2 = bx * NTHR + tid; e2 < BB * HH2; e2 += NBLK * NTHR) {
            int d2 = e2 >> 14;
            int b = (e2 >> 8) & 63;
            int ip = (e2 & 255) * 2;
            const float* bhh = d2 ? bhh_b : bhh_f;
            float2 hr = *(const float2*)&bhh[ip];
            float2 hz = *(const float2*)&bhh[HH2 + ip];
            float2 hn = *(const float2*)&bhh[2 * HH2 + ip];
#pragma unroll
            for (int q = 0; q < KS_GRU; q++) {
                size_t base = (((size_t)q * 2 + d2) * BB + b) * G3;
                float2 a0 = *(const float2*)&g_ghp[base + ip];
                float2 a1 = *(const float2*)&g_ghp[base + HH2 + ip];
                float2 a2v = *(const float2*)&g_ghp[base + 2 * HH2 + ip];
                hr.x += a0.x; hr.y += a0.y;
                hz.x += a1.x; hz.y += a1.y;
                hn.x += a2v.x; hn.y += a2v.y;
            }
            size_t xb = (((size_t)d2 * SS + t) * BB + b) * G3;
            float2 xr = *(const float2*)&g_xproj[xb + ip];
            float2 xz = *(const float2*)&g_xproj[xb + HH2 + ip];
            float2 xn = *(const float2*)&g_xproj[xb + 2 * HH2 + ip];
            float2 hp = make_float2(0.f, 0.f);
            if (t > 0)
                hp = d2 ? *(const float2*)&g_mem[((size_t)(SS - t) * BB + b) * HH + HH2 + ip]
                        : *(const float2*)&g_mem[((size_t)(t - 1) * BB + b) * HH + ip];
            float2 h;
            {
                float r = sigm(xr.x + hr.x);
                float z = sigm(xz.x + hz.x);
                float n2 = tanhf(xn.x + r * hn.x);
                h.x = (1.f - z) * n2 + z * hp.x;
            }
            {
                float r = sigm(xr.y + hr.y);
                float z = sigm(xz.y + hz.y);
                float n2 = tanhf(xn.y + r * hn.y);
                h.y = (1.f - z) * n2 + z * hp.y;
            }
            if (d2 == 0) *(float2*)&g_mem[((size_t)t * BB + b) * HH + ip] = h;
            else         *(float2*)&g_mem[((size_t)(SS - 1 - t) * BB + b) * HH + HH2 + ip] = h;
        }
        gsync(bar_id);
    }
}

// ---------------- emo GEMM phase: N=128 tiles x KS=16, k-chunk 64, double-buffered ----------------
template <int AMODE>
__device__ __forceinline__ void emo_gemm(int t, const float* __restrict__ W,
                                         float* __restrict__ dst,
                                         float (*As)[16][68], float (*Ws)[16][260],
                                         int tx16, int ty16)
{
    const int tid = threadIdx.x;
    const int w = blockIdx.x;
    if (w >= 8 * KS_EMO) return;
    const int nt = w >> 4;       // 8 N-tiles of 128
    const int ks = w & 15;       // 16 K-chunks of 64
    const int Nbase = nt * 128;
    const int k0 = ks * 64;

    ull acc[4][4];
#pragma unroll
    for (int i = 0; i < 4; i++)
#pragma unroll
        for (int j = 0; j < 4; j++) acc[i][j] = 0ull;

    float va[4], vw[8];
#pragma unroll
    for (int p = 0; p < 4; p++) {
        int i = tid + p * 256;
        int m = i >> 4, kg = k0 + (i & 15);
        float v;
        if (AMODE == 0)
            v = (t == 0) ? g_mem[(size_t)m * HH + kg] : g_gated[(size_t)m * HH + kg];
        else
            v = g_hln[(size_t)m * HH + kg];
        va[p] = v;
    }
#pragma unroll
    for (int p = 0; p < 8; p++) {
        int i = tid + p * 256;
        int n = i >> 4, kg = k0 + (i & 15);
        vw[p] = W[(size_t)(Nbase + n) * HH + kg];
    }
#pragma unroll
    for (int p = 0; p < 4; p++) {
        int i = tid + p * 256;
        As[0][i & 15][i >> 4] = va[p];
    }
#pragma unroll
    for (int p = 0; p < 8; p++) {
        int i = tid + p * 256;
        Ws[0][i & 15][i >> 4] = vw[p];
    }
    __syncthreads();

#pragma unroll
    for (int it = 0; it < 4; it++) {
        const bool more = (it + 1 < 4);
        if (more) {
            int kg0 = k0 + (it + 1) * 16;
#pragma unroll
            for (int p = 0; p < 4; p++) {
                int i = tid + p * 256;
                int m = i >> 4, kg = kg0 + (i & 15);
                float v;
                if (AMODE == 0)
                    v = (t == 0) ? g_mem[(size_t)m * HH + kg] : g_gated[(size_t)m * HH + kg];
                else
                    v = g_hln[(size_t)m * HH + kg];
                va[p] = v;
            }
#pragma unroll
            for (int p = 0; p < 8; p++) {
                int i = tid + p * 256;
                int n = i >> 4, kg = kg0 + (i & 15);
                vw[p] = W[(size_t)(Nbase + n) * HH + kg];
            }
        }
        mk128(acc, (const float (*)[68])As[it & 1], (const float (*)[260])Ws[it & 1],
              tx16, ty16);
        if (more) {
#pragma unroll
            for (int p = 0; p < 4; p++) {
                int i = tid + p * 256;
                As[(it + 1) & 1][i & 15][i >> 4] = va[p];
            }
#pragma unroll
            for (int p = 0; p < 8; p++) {
                int i = tid + p * 256;
                Ws[(it + 1) & 1][i & 15][i >> 4] = vw[p];
            }
            __syncthreads();
        }
    }
#pragma unroll
    for (int i2 = 0; i2 < 4; i2++) {
        int m = ty16 * 4 + i2;
        size_t rowb = ((size_t)ks * BB + m) * HH;
#pragma unroll
        for (int jp = 0; jp < 4; jp++) {
            int col = Nbase + 2 * tx16 + 32 * jp;
            F2U u; u.u = acc[i2][jp];
            *(float2*)&dst[rowb + col] = u.f;
        }
    }
}

// ---------------- gate GEMM phase: N=4096 (16x256), K pad 2160 (9x240), double-buffered ----------------
__device__ __forceinline__ void gate_gemm(int t,
    const float* __restrict__ Wf, const float* __restrict__ Wi,
    const float* __restrict__ Wo, const float* __restrict__ Wc,
    const float* __restrict__ outp, const float* __restrict__ spk,
    const float* __restrict__ pos,
    float (*As)[16][68], float (*Ws)[16][260], int tx, int ty)
{
    const int tid = threadIdx.x;
    const int w = blockIdx.x;
    if (w >= 16 * KS_GATE) return;
    const int nt = w / KS_GATE;
    const int ks = w % KS_GATE;
    const int Nbase = nt * 256;
    const int gate = Nbase >> 10;
    const float* W = (gate == 0) ? Wf : (gate == 1) ? Wi : (gate == 2) ? Wo : Wc;
    const int wrow = Nbase & 1023;
    const int k0 = ks * 240;

    ull acc[8][4];
#pragma unroll
    for (int i = 0; i < 8; i++)
#pragma unroll
        for (int j = 0; j < 4; j++) acc[i][j] = 0ull;

    float va[4], vw[16];
#pragma unroll
    for (int p = 0; p < 4; p++) {
        int i = tid + p * 256;
        int m = i >> 4, kg = k0 + (i & 15);
        float v = 0.f;
        if (kg < 1024)      v = g_mem[((size_t)t * BB + m) * HH + kg];
        else if (kg < 2048) v = outp[((size_t)m * SS + (t - 1)) * HH + (kg - 1024)];
        else if (kg < 2064) v = spk[((size_t)m * SS + t) * SPKD + (kg - 2048)];
        else if (kg < 2080) v = pos[((size_t)m * SS + t) * SPKD + (kg - 2064)];
        va[p] = v;
    }
#pragma unroll
    for (int p = 0; p < 16; p++) {
        int i = tid + p * 256;
        int n = i >> 4, kg = k0 + (i & 15);
        vw[p] = (kg < GINK) ? W[(size_t)(wrow + n) * GINK + kg] : 0.f;
    }
#pragma unroll
    for (int p = 0; p < 4; p++) {
        int i = tid + p * 256;
        As[0][i & 15][i >> 4] = va[p];
    }
#pragma unroll
    for (int p = 0; p < 16; p++) {
        int i = tid + p * 256;
        Ws[0][i & 15][i >> 4] = vw[p];
    }
    __syncthreads();

    for (int it = 0; it < 15; it++) {
        const bool more = (it + 1 < 15);
        if (more) {
            int kg0 = k0 + (it + 1) * 16;
#pragma unroll
            for (int p = 0; p < 4; p++) {
                int i = tid + p * 256;
                int m = i >> 4, kg = kg0 + (i & 15);
                float v = 0.f;
                if (kg < 1024)      v = g_mem[((size_t)t * BB + m) * HH + kg];
                else if (kg < 2048) v = outp[((size_t)m * SS + (t - 1)) * HH + (kg - 1024)];
                else if (kg < 2064) v = spk[((size_t)m * SS + t) * SPKD + (kg - 2048)];
                else if (kg < 2080) v = pos[((size_t)m * SS + t) * SPKD + (kg - 2064)];
                va[p] = v;
            }
#pragma unroll
            for (int p = 0; p < 16; p++) {
                int i = tid + p * 256;
                int n = i >> 4, kg = kg0 + (i & 15);
                vw[p] = (kg < GINK) ? W[(size_t)(wrow + n) * GINK + kg] : 0.f;
            }
        }
        mk64(acc, (const float (*)[68])As[it & 1], (const float (*)[260])Ws[it & 1], tx, ty);
        if (more) {
#pragma unroll
            for (int p = 0; p < 4; p++) {
                int i = tid + p * 256;
                As[(it + 1) & 1][i & 15][i >> 4] = va[p];
            }
#pragma unroll
            for (int p = 0; p < 16; p++) {
                int i = tid + p * 256;
                Ws[(it + 1) & 1][i & 15][i >> 4] = vw[p];
            }
            __syncthreads();
        }
    }
#pragma unroll
    for (int i2 = 0; i2 < 8; i2++) {
        int m = ty * 8 + i2;
        size_t rowb = ((size_t)ks * BB + m) * 4096;
#pragma unroll
        for (int jp = 0; jp < 4; jp++) {
            int col = Nbase + 2 * tx + 64 * jp;
            F2U u; u.u = acc[i2][jp];
            *(float2*)&g_gpre[rowb + col] = u.f;
        }
    }
}

// ---------------- persistent gating kernel: 512 steps ----------------
__global__ __launch_bounds__(NTHR, 1) void gating_persistent(
    const float* __restrict__ spk, const float* __restrict__ pos,
    const float* __restrict__ Wfw, const float* __restrict__ bfb,
    const float* __restrict__ Wiw, const float* __restrict__ bib,
    const float* __restrict__ Wow, const float* __restrict__ bob,
    const float* __restrict__ Wcw, const float* __restrict__ bcb,
    const float* __restrict__ W1e, const float* __restrict__ b1e,
    const float* __restrict__ gln, const float* __restrict__ beta,
    const float* __restrict__ W2e, const float* __restrict__ b2e,
    float* __restrict__ out)
{
    __shared__ __align__(16) float As[2][16][68];
    __shared__ __align__(16) float Ws[2][16][260];
    __shared__ float sred[NTHR];
    __shared__ float stats[2];
    const int tid = threadIdx.x;
    const int tx = tid & 31, ty = tid >> 5;
    const int tx16 = tid & 15, ty16 = tid >> 4;
    const int bx = blockIdx.x;
    unsigned int bar_id = 0;

    for (int t = 0; t < SS; t++) {
        if (t > 0) {
            gate_gemm(t, Wfw, Wiw, Wow, Wcw, out, spk, pos, As, Ws, tx, ty);
            gsync(bar_id);
            // gate combine (float2): 32768 pairs, single pass
            for (int e2 = bx * NTHR + tid; e2 < BB * HH / 2; e2 += NBLK * NTHR) {
                int b = e2 >> 9;
                int ip = (e2 & 511) * 2;
                float2 f  = *(const float2*)&bfb[ip];
                float2 ig = *(const float2*)&bib[ip];
                float2 o  = *(const float2*)&bob[ip];
                float2 c  = *(const float2*)&bcb[ip];
#pragma unroll
                for (int q = 0; q < KS_GATE; q++) {
                    size_t base = ((size_t)q * BB + b) * 4096;
                    float2 p0 = *(const float2*)&g_gpre[base + ip];
                    float2 p1 = *(const float2*)&g_gpre[base + 1024 + ip];
                    float2 p2 = *(const float2*)&g_gpre[base + 2048 + ip];
                    float2 p3 = *(const float2*)&g_gpre[base + 3072 + ip];
                    f.x += p0.x;  f.y += p0.y;
                    ig.x += p1.x; ig.y += p1.y;
                    o.x += p2.x;  o.y += p2.y;
                    c.x += p3.x;  c.y += p3.y;
                }
                float2 prev = *(const float2*)&out[((size_t)b * SS + (t - 1)) * HH + ip];
                float2 g;
                {
                    float ff = sigm(f.x), ii = sigm(ig.x), oo = sigm(o.x), cc = tanhf(c.x);
                    g.x = oo * tanhf(ff * prev.x + ii * cc);
                }
                {
                    float ff = sigm(f.y), ii = sigm(ig.y), oo = sigm(o.y), cc = tanhf(c.y);
                    g.y = oo * tanhf(ff * prev.y + ii * cc);
                }
                *(float2*)&g_gated[(size_t)b * HH + ip] = g;
            }
            gsync(bar_id);
        }

        // emo GEMM1
        emo_gemm<0>(t, W1e, g_h1p, As, Ws, tx16, ty16);
        gsync(bar_id);

        // LayerNorm + ReLU (blocks 0..63), float2 partial loads
        if (bx < BB) {
            const int b = bx;
            float2 v[2];
            float lsum = 0.f, lsq = 0.f;
#pragma unroll
            for (int j = 0; j < 2; j++) {
                int ip = (tid + j * NTHR) * 2;
                float2 x = *(const float2*)&b1e[ip];
#pragma unroll
                for (int q = 0; q < KS_EMO; q++) {
                    float2 pp = *(const float2*)&g_h1p[((size_t)q * BB + b) * HH + ip];
                    x.x += pp.x; x.y += pp.y;
                }
                v[j] = x;
                lsum += x.x + x.y;
                lsq += x.x * x.x + x.y * x.y;
            }
            sred[tid] = lsum; __syncthreads();
            for (int s2 = NTHR / 2; s2 > 0; s2 >>= 1) {
                if (tid < s2) sred[tid] += sred[tid + s2];
                __syncthreads();
            }
            if (tid == 0) stats[0] = sred[0] * (1.f / 1024.f);
            __syncthreads();
            sred[tid] = lsq; __syncthreads();
            for (int s2 = NTHR / 2; s2 > 0; s2 >>= 1) {
                if (tid < s2) sred[tid] += sred[tid + s2];
                __syncthreads();
            }
            if (tid == 0) stats[1] = sred[0] * (1.f / 1024.f);
            __syncthreads();
            float mu = stats[0];
            float var = stats[1] - mu * mu;
            float rs = rsqrtf(var + 1e-5f);
#pragma unroll
            for (int j = 0; j < 2; j++) {
                int ip = (tid + j * NTHR) * 2;
                float2 gl = *(const float2*)&gln[ip];
                float2 bt = *(const float2*)&beta[ip];
                float2 y;
                y.x = (v[j].x - mu) * rs * gl.x + bt.x;
                y.y = (v[j].y - mu) * rs * gl.y + bt.y;
                y.x = y.x > 0.f ? y.x : 0.f;
                y.y = y.y > 0.f ? y.y : 0.f;
                *(float2*)&g_hln[(size_t)b * HH + ip] = y;
            }
        }
        gsync(bar_id);

        // emo GEMM2
        emo_gemm<1>(t, W2e, g_o2p, As, Ws, tx16, ty16);
        gsync(bar_id);

        // finalize (float2): 32768 pairs, single pass
        for (int e2 = bx * NTHR + tid; e2 < BB * HH / 2; e2 += NBLK * NTHR) {
            int b = e2 >> 9;
            int ip = (e2 & 511) * 2;
            float2 x = *(const float2*)&b2e[ip];
#pragma unroll
            for (int q = 0; q < KS_EMO; q++) {
                float2 pp = *(const float2*)&g_o2p[((size_t)q * BB + b) * HH + ip];
                x.x += pp.x; x.y += pp.y;
            }
            float2 res = (t == 0) ? *(const float2*)&g_mem[(size_t)b * HH + ip]
                                  : *(const float2*)&g_gated[(size_t)b * HH + ip];
            float2 oo;
            oo.x = x.x + res.x;
            oo.y = x.y + res.y;
            *(float2*)&out[((size_t)b * SS + t) * HH + ip] = oo;
        }
        gsync(bar_id);
    }
}

// ---------------- host launcher: 5 graph nodes total ----------------
extern "C" void kernel_launch(void* const* d_in, const int* in_sizes, int n_in,
                              void* d_out, int out_size)
{
    (void)in_sizes; (void)n_in; (void)out_size;
    const float* uf    = (const float*)d_in[0];
    const float* spk   = (const float*)d_in[1];
    const float* pos   = (const float*)d_in[2];
    const float* Wih_f = (const float*)d_in[3];
    const float* Whh_f = (const float*)d_in[4];
    const float* bih_f = (const float*)d_in[5];
    const float* bhh_f = (const float*)d_in[6];
    const float* Wih_b = (const float*)d_in[7];
    const float* Whh_b = (const float*)d_in[8];
    const float* bih_b = (const float*)d_in[9];
    const float* bhh_b = (const float*)d_in[10];
    const float* Wfw   = (const float*)d_in[11];
    const float* bfb   = (const float*)d_in[12];
    const float* Wiw   = (const float*)d_in[13];
    const float* bib   = (const float*)d_in[14];
    const float* Wow   = (const float*)d_in[15];
    const float* bob   = (const float*)d_in[16];
    const float* Wcw   = (const float*)d_in[17];
    const float* bcb   = (const float*)d_in[18];
    const float* W1e   = (const float*)d_in[19];
    const float* b1e   = (const float*)d_in[20];
    const float* g_ln  = (const float*)d_in[21];
    const float* beta  = (const float*)d_in[22];
    const float* W2e   = (const float*)d_in[23];
    const float* b2e   = (const float*)d_in[24];
    float* out = (float*)d_out;

    // 1) x projections for both GRU directions (parallel, big grid)
    xproj_kernel<<<dim3(256, 12, 2), 256>>>(uf, Wih_f, bih_f, Wih_b, bih_b);

    // 2) persistent bidirectional GRU recurrence
    reset_bar_k<<<1, 1>>>();
    gru_persistent<<<NBLK, NTHR>>>(Whh_f, Whh_b, bhh_f, bhh_b);

    // 3) persistent dialogue gating loop
    reset_bar_k<<<1, 1>>>();
    gating_persistent<<<NBLK, NTHR>>>(spk, pos, Wfw, bfb, Wiw, bib, Wow, bob,
                                      Wcw, bcb, W1e, b1e, g_ln, beta, W2e, b2e, out);
}